// round 13
// baseline (speedup 1.0000x reference)
#include <cuda_runtime.h>
#include <cuda_bf16.h>
#include <cstdint>

#define BSZ 64
#define NJ  44
#define HS  256
#define REPF 512
#define NLAY 4
#define NROWS (BSZ*NJ)
#define RPB 32
#define GBLK 88

// ---------------- persistent device state ----------------
__device__ float g_h[NROWS*HS];
__device__ float g_agg[NROWS*HS];
__device__ float g_P[NROWS*HS];
__device__ float g_Q[NROWS*HS];
__device__ float g_P2[NROWS*HS];
__device__ float g_Q2[NROWS*HS];
__device__ float g_x[NROWS*3];
__device__ float g_x0[NROWS*3];
__device__ float g_d[BSZ*NJ*NJ];
__device__ float g_d0[BSZ*NJ*NJ];
__device__ float g_cdiff[BSZ*NJ*NJ*3];
__device__ unsigned int g_W2T8[12*256*64];      // e4m3x4 [m][n][k/4]
__device__ unsigned int g_WpqT[12*2*256*256];   // tf32 [m][half][n][k]
__device__ unsigned int g_Wn1T[8*256*512];      // tf32 [m][n][k]
__device__ unsigned int g_Wn2T[8*256*256];      // tf32 [m][n][k]

__device__ __forceinline__ float silu_f(float x) {
    return x / (1.0f + __expf(-x));
}
__device__ __forceinline__ float silu_t(float x) {
    float t;
    asm("tanh.approx.f32 %0, %1;" : "=f"(t) : "f"(0.5f*x));
    return 0.5f*x*(1.0f + t);
}
__device__ __forceinline__ unsigned int f2tf32(float v) {
    unsigned int u;
    asm("cvt.rna.tf32.f32 %0, %1;" : "=r"(u) : "f"(v));
    return u;
}
// pack 4 floats -> e4m3x4 (k ascending in byte order)
__device__ __forceinline__ unsigned int pack4e(float a, float b, float c, float d) {
    unsigned short lo, hi;
    asm("cvt.rn.satfinite.e4m3x2.f32 %0, %1, %2;" : "=h"(lo) : "f"(b), "f"(a));
    asm("cvt.rn.satfinite.e4m3x2.f32 %0, %1, %2;" : "=h"(hi) : "f"(d), "f"(c));
    unsigned int r;
    asm("mov.b32 %0, {%1, %2};" : "=r"(r) : "h"(lo), "h"(hi));
    return r;
}
__device__ __forceinline__ uint32_t sptr(const void* p) {
    uint32_t a;
    asm("{ .reg .u64 t; cvta.to.shared.u64 t, %1; cvt.u32.u64 %0, t; }" : "=r"(a) : "l"(p));
    return a;
}
__device__ __forceinline__ void mma32(float c[4], unsigned a0, unsigned a1,
                                      unsigned a2, unsigned a3,
                                      unsigned b0, unsigned b1) {
    asm volatile("mma.sync.aligned.m16n8k32.row.col.f32.e4m3.e4m3.f32 "
        "{%0,%1,%2,%3}, {%4,%5,%6,%7}, {%8,%9}, {%0,%1,%2,%3};"
        : "+f"(c[0]), "+f"(c[1]), "+f"(c[2]), "+f"(c[3])
        : "r"(a0), "r"(a1), "r"(a2), "r"(a3), "r"(b0), "r"(b1));
}
__device__ __forceinline__ void mma8(float c[4], unsigned a0, unsigned a1,
                                     unsigned a2, unsigned a3,
                                     unsigned b0, unsigned b1) {
    asm volatile("mma.sync.aligned.m16n8k8.row.col.f32.tf32.tf32.f32 "
        "{%0,%1,%2,%3}, {%4,%5,%6,%7}, {%8,%9}, {%0,%1,%2,%3};"
        : "+f"(c[0]), "+f"(c[1]), "+f"(c[2]), "+f"(c[3])
        : "r"(a0), "r"(a1), "r"(a2), "r"(a3), "r"(b0), "r"(b1));
}
#define LDSM4(r0, r1, r2, r3, addr) \
    asm volatile("ldmatrix.sync.aligned.m8n8.x4.shared.b16 {%0,%1,%2,%3}, [%4];" \
        : "=r"(r0), "=r"(r1), "=r"(r2), "=r"(r3) : "r"(addr))
#define CPA16(dst, src) asm volatile("cp.async.cg.shared.global [%0], [%1], 16;" :: "r"(dst), "l"(src) : "memory")
#define CPA_COMMIT()    asm volatile("cp.async.commit_group;" ::: "memory")
#define CPA_WAIT0()     asm volatile("cp.async.wait_group 0;" ::: "memory")

// ---------------- weight prep ----------------
__global__ void k_prepall(const float* __restrict__ We2, const float* __restrict__ Wc2,
                          const float* __restrict__ We1, const float* __restrict__ Wc1,
                          const float* __restrict__ Wn1, const float* __restrict__ Wn2) {
    __shared__ float tile[32][33];
    int z = blockIdx.z;
    int k0 = blockIdx.x*32, n0 = blockIdx.y*32;
    int tx = threadIdx.x, ty = threadIdx.y;
    int tid = ty*32 + tx;
    if (z < 12) {
        int m = z;
        const float* src = (m < 8) ? We2 + (size_t)m*HS*HS : Wc2 + (size_t)(m-8)*HS*HS;
        unsigned int* dst = g_W2T8 + (size_t)m*256*64;
        #pragma unroll
        for (int q = 0; q < 4; q++)
            tile[ty + 8*q][tx] = src[(size_t)(k0 + ty + 8*q)*HS + n0 + tx];
        __syncthreads();
        {
            int nl = tid >> 3, p = tid & 7;   // 32 n x 8 u32 (32 k) per block
            dst[(size_t)(n0 + nl)*64 + (k0 >> 2) + p] =
                pack4e(tile[4*p][nl], tile[4*p+1][nl], tile[4*p+2][nl], tile[4*p+3][nl]);
        }
        return;
    }
    int v = z - 12;
    const float* src; unsigned int* dst; int stride, koff;
    if (v < 24) {
        int m = v >> 1, half = v & 1;
        src = ((m < 8) ? We1 + (size_t)m*514*HS : Wc1 + (size_t)(m-8)*514*HS)
              + (size_t)half*HS*HS;
        dst = g_WpqT + ((size_t)m*2 + half)*65536; stride = 256; koff = 0;
    } else if (v < 40) {
        int u = v - 24, m = u >> 1, kh = u & 1;
        src = Wn1 + (size_t)m*512*HS + (size_t)kh*HS*HS;
        dst = g_Wn1T + (size_t)m*131072; stride = 512; koff = kh*256;
    } else {
        int m = v - 40;
        src = Wn2 + (size_t)m*HS*HS;
        dst = g_Wn2T + (size_t)m*65536; stride = 256; koff = 0;
    }
    #pragma unroll
    for (int q = 0; q < 4; q++)
        tile[ty + 8*q][tx] = src[(size_t)(k0 + ty + 8*q)*HS + n0 + tx];
    __syncthreads();
    for (int o = tid; o < 1024; o += 256) {
        int nl = o >> 5, kk = o & 31;
        dst[(size_t)(n0 + nl)*stride + koff + k0 + kk] = f2tf32(tile[kk][nl]);
    }
}

// ---------------- k_fused smem layout (fp8) ----------------
// As u32 [96][68] = 6528 ; Bs u32 2x[256][20] = 10240
#define F_OD   16768
#define F_OD0  16864
#define F_OMK  16960
#define F_OPS  17056
#define F_OPHI 17824
#define FUSED_FLOATS 17920
#define FUSED_BYTES (FUSED_FLOATS*4)
#define PQM_BYTES   ((RPB*260 + 2*256*36)*4)
#define NODEM_BYTES ((RPB*516 + 2*256*36 + RPB*260)*4)

// =====================================================================
// Fused edge/coord MLP; block = (b, i-pair): M=96, N=256, fp8 layer-2.
// =====================================================================
__global__ __launch_bounds__(256, 2) void k_fused(
    const float* __restrict__ W1,
    int mW2,
    const float* __restrict__ b2,
    const float* __restrict__ em,
    const float* __restrict__ W3,
    const float* __restrict__ nm,
    int mode, int pqbuf)
{
    extern __shared__ float S[];
    unsigned int* As = (unsigned int*)S;           // [96][68]
    unsigned int* Bs = As + 96*68;                 // 2 x [256][20]
    const unsigned int* W2T = g_W2T8 + (size_t)mW2*256*64;
    const float* Pp = pqbuf ? g_P2 : g_P;
    const float* Qp = pqbuf ? g_Q2 : g_Q;

    int tid = threadIdx.x, warp = tid >> 5, lane = tid & 31;
    int lane4 = lane >> 2, lanem = lane & 3;
    int b = blockIdx.x / 22, pr = blockIdx.x % 22;
    int i0 = 2*pr;
    uint32_t bsm = sptr(Bs);
    uint32_t asmb = sptr(As);

    // B chunk 0 -> buf 0 (16 u32/row, one row per thread)
    #pragma unroll
    for (int q = 0; q < 4; q++)
        CPA16(bsm + (tid*20 + q*4)*4, &W2T[(size_t)tid*64 + q*4]);
    CPA_COMMIT();

    if (tid < 96) {
        int g = tid / 48, j = tid % 48;
        float dv = 0.f, d0v = 0.f, mv = 0.f;
        if (j < NJ) {
            int e = (b*NJ + i0 + g)*NJ + j;
            dv = g_d[e]; d0v = g_d0[e]; mv = em[e];
        }
        S[F_OD + tid] = dv; S[F_OD0 + tid] = d0v; S[F_OMK + tid] = mv;
    }
    __syncthreads();

    // ---- phase 1: A[j][4ch-u32] = e4m3x4(silu(P+Q+wd*d+wd0*d0)) ----
    {
        int cp4 = tid & 63, jh = tid >> 6;
        int j0 = jh * 11;
        float4 Pv0 = *(const float4*)&Pp[(size_t)(b*NJ + i0    )*HS + 4*cp4];
        float4 Pv1 = *(const float4*)&Pp[(size_t)(b*NJ + i0 + 1)*HS + 4*cp4];
        float4 wdv = *(const float4*)&W1[512*HS + 4*cp4];
        float4 wd0v= *(const float4*)&W1[513*HS + 4*cp4];
        const float* qbase = Qp + (size_t)b*NJ*HS + 4*cp4;
        float4 qv[11];
        #pragma unroll
        for (int u = 0; u < 11; u++)
            qv[u] = *(const float4*)&qbase[(size_t)(j0 + u)*HS];
        #pragma unroll
        for (int u = 0; u < 11; u++) {
            int j = j0 + u;
            float dj0 = S[F_OD + j],      d0j0 = S[F_OD0 + j];
            float dj1 = S[F_OD + 48 + j], d0j1 = S[F_OD0 + 48 + j];
            float v00 = Pv0.x + qv[u].x + wdv.x*dj0 + wd0v.x*d0j0;
            float v01 = Pv0.y + qv[u].y + wdv.y*dj0 + wd0v.y*d0j0;
            float v02 = Pv0.z + qv[u].z + wdv.z*dj0 + wd0v.z*d0j0;
            float v03 = Pv0.w + qv[u].w + wdv.w*dj0 + wd0v.w*d0j0;
            float v10 = Pv1.x + qv[u].x + wdv.x*dj1 + wd0v.x*d0j1;
            float v11 = Pv1.y + qv[u].y + wdv.y*dj1 + wd0v.y*d0j1;
            float v12 = Pv1.z + qv[u].z + wdv.z*dj1 + wd0v.z*d0j1;
            float v13 = Pv1.w + qv[u].w + wdv.w*dj1 + wd0v.w*d0j1;
            As[j*68 + cp4] =
                pack4e(silu_t(v00), silu_t(v01), silu_t(v02), silu_t(v03));
            As[(48 + j)*68 + cp4] =
                pack4e(silu_t(v10), silu_t(v11), silu_t(v12), silu_t(v13));
        }
        for (int p = tid; p < 4*68; p += 256) {
            As[44*68 + p] = 0u;
            As[92*68 + p] = 0u;
        }
    }
    CPA_WAIT0();
    __syncthreads();

    // ---- phase 2: 4 chunks of K=64 fp8, ldmatrix frags, cp.async dbl-buf ----
    float acc[6][4][4];
    #pragma unroll
    for (int mt = 0; mt < 6; mt++)
        #pragma unroll
        for (int nt = 0; nt < 4; nt++)
            #pragma unroll
            for (int q = 0; q < 4; q++) acc[mt][nt][q] = 0.f;

    int l7 = lane & 7, sel = lane >> 3;
    uint32_t abase = asmb + ((((sel & 1)*8 + l7)*68) + (sel >> 1)*4)*4;
    uint32_t baddr[2];
    #pragma unroll
    for (int t = 0; t < 2; t++)
        baddr[t] = bsm + (((warp*32 + t*16 + (sel >> 1)*8 + l7)*20) + (sel & 1)*4)*4;

    for (int kc = 0; kc < 4; kc++) {
        if (kc < 3) {
            uint32_t dsm = bsm + (((kc+1) & 1) ? 256*20*4 : 0);
            #pragma unroll
            for (int q = 0; q < 4; q++)
                CPA16(dsm + (tid*20 + q*4)*4, &W2T[(size_t)tid*64 + (kc+1)*16 + q*4]);
            CPA_COMMIT();
        }
        uint32_t boff = (kc & 1) ? 256*20*4 : 0;
        #pragma unroll
        for (int s = 0; s < 2; s++) {
            uint32_t koff = (uint32_t)(kc*16 + s*8)*4;
            unsigned int bb[8];
            LDSM4(bb[0], bb[1], bb[2], bb[3], baddr[0] + boff + s*8*4);
            LDSM4(bb[4], bb[5], bb[6], bb[7], baddr[1] + boff + s*8*4);
            #pragma unroll
            for (int mt = 0; mt < 6; mt++) {
                unsigned int a0, a1, a2, a3;
                LDSM4(a0, a1, a2, a3, abase + (uint32_t)mt*16*68*4 + koff);
                mma32(acc[mt][0], a0, a1, a2, a3, bb[0], bb[1]);
                mma32(acc[mt][1], a0, a1, a2, a3, bb[2], bb[3]);
                mma32(acc[mt][2], a0, a1, a2, a3, bb[4], bb[5]);
                mma32(acc[mt][3], a0, a1, a2, a3, bb[6], bb[7]);
            }
        }
        if (kc < 3) CPA_WAIT0();
        __syncthreads();
    }

    // ---- epilogue ----
    float msk[12];
    #pragma unroll
    for (int mt = 0; mt < 6; mt++) {
        msk[2*mt]   = S[F_OMK + mt*16 + lane4];
        msk[2*mt+1] = S[F_OMK + mt*16 + lane4 + 8];
    }
    if (mode == 0) {
        #pragma unroll
        for (int g = 0; g < 2; g++) {
            size_t rowbase = (size_t)(b*NJ + i0 + g)*HS;
            #pragma unroll
            for (int nt = 0; nt < 4; nt++) {
                int n = warp*32 + nt*8 + lanem*2;
                float2 bb = *(const float2*)&b2[n];
                float s0 = 0.f, s1 = 0.f;
                #pragma unroll
                for (int mm = 0; mm < 3; mm++) {
                    int mt = g*3 + mm;
                    s0 += silu_t(acc[mt][nt][0] + bb.x)*msk[2*mt]
                        + silu_t(acc[mt][nt][2] + bb.x)*msk[2*mt+1];
                    s1 += silu_t(acc[mt][nt][1] + bb.y)*msk[2*mt]
                        + silu_t(acc[mt][nt][3] + bb.y)*msk[2*mt+1];
                }
                #pragma unroll
                for (int off = 4; off <= 16; off <<= 1) {
                    s0 += __shfl_xor_sync(0xffffffffu, s0, off);
                    s1 += __shfl_xor_sync(0xffffffffu, s1, off);
                }
                if (lane4 == 0)
                    *(float2*)&g_agg[rowbase + n] = make_float2(s0*0.01f, s1*0.01f);
            }
        }
    } else {
        float ph[12];
        #pragma unroll
        for (int q = 0; q < 12; q++) ph[q] = 0.f;
        #pragma unroll
        for (int nt = 0; nt < 4; nt++) {
            int n = warp*32 + nt*8 + lanem*2;
            float2 bb = *(const float2*)&b2[n];
            float2 w3 = *(const float2*)&W3[n];
            #pragma unroll
            for (int mt = 0; mt < 6; mt++) {
                ph[2*mt]   += silu_t(acc[mt][nt][0] + bb.x)*w3.x
                            + silu_t(acc[mt][nt][1] + bb.y)*w3.y;
                ph[2*mt+1] += silu_t(acc[mt][nt][2] + bb.x)*w3.x
                            + silu_t(acc[mt][nt][3] + bb.y)*w3.y;
            }
        }
        #pragma unroll
        for (int q = 0; q < 12; q++) {
            ph[q] += __shfl_xor_sync(0xffffffffu, ph[q], 1);
            ph[q] += __shfl_xor_sync(0xffffffffu, ph[q], 2);
        }
        if (lanem == 0) {
            #pragma unroll
            for (int mt = 0; mt < 6; mt++) {
                S[F_OPS + warp*96 + mt*16 + lane4]     = ph[2*mt];
                S[F_OPS + warp*96 + mt*16 + lane4 + 8] = ph[2*mt+1];
            }
        }
        __syncthreads();
        if (tid < 96) {
            float p = 0.f;
            #pragma unroll
            for (int w = 0; w < 8; w++) p += S[F_OPS + w*96 + tid];
            S[F_OPHI + tid] = p * S[F_OMK + tid];
        }
        __syncthreads();
        if (tid < 48) {
            int pair = tid >> 3, t8 = tid & 7;
            if (pair < 6) {
                int g = pair / 3, d = pair % 3;
                int i = i0 + g;
                const float* cd = g_cdiff + ((size_t)((b*NJ + i)*NJ))*3 + d;
                float s = 0.f;
                for (int j = t8; j < NJ; j += 8)
                    s += cd[j*3] * S[F_OPHI + g*48 + j];
                s += __shfl_down_sync(0xffffffffu, s, 4);
                s += __shfl_down_sync(0xffffffffu, s, 2);
                s += __shfl_down_sync(0xffffffffu, s, 1);
                if (t8 == 0) {
                    float m = nm[b*NJ + i];
                    int xi = (b*NJ + i)*3 + d;
                    g_x[xi] = (g_x[xi] + s*0.01f) * m;
                }
            }
        }
    }
}

// =====================================================================
// P/Q projection via tf32 mma, M=32/block, grid (88, 2, nsets).
// =====================================================================
__global__ __launch_bounds__(256) void k_pqm(
    int mWA, const float* __restrict__ bA,
    int mWB, const float* __restrict__ bB)
{
    extern __shared__ float S[];
    unsigned int* As = (unsigned int*)S;
    unsigned int* Bs = As + RPB*260;
    int tid = threadIdx.x, warp = tid >> 5, lane = tid & 31;
    int lane4 = lane >> 2, lanem = lane & 3;
    int r0 = blockIdx.x * RPB, half = blockIdx.y, set = blockIdx.z;
    int mW = set ? mWB : mWA;
    const float* b1 = set ? bB : bA;
    const unsigned int* BT = g_WpqT + ((size_t)mW*2 + half)*65536;
    uint32_t bsm = sptr(Bs);

    #pragma unroll
    for (int q = 0; q < 8; q++)
        CPA16(bsm + (tid*36 + q*4)*4, &BT[(size_t)tid*256 + q*4]);
    CPA_COMMIT();

    for (int idx = tid; idx < RPB*256; idx += 256) {
        int row = idx >> 8, k = idx & 255;
        float v = 0.f;
        int gr = r0 + row;
        if (gr < NROWS) v = g_h[(size_t)gr*HS + k];
        As[row*260 + k] = f2tf32(v);
    }
    CPA_WAIT0();
    __syncthreads();

    float acc[2][4][4];
    #pragma unroll
    for (int mt = 0; mt < 2; mt++)
        #pragma unroll
        for (int nt = 0; nt < 4; nt++)
            #pragma unroll
            for (int q = 0; q < 4; q++) acc[mt][nt][q] = 0.f;

    for (int kc = 0; kc < 8; kc++) {
        if (kc < 7) {
            uint32_t dsm = bsm + (((kc+1) & 1) ? 256*36*4 : 0);
            #pragma unroll
            for (int q = 0; q < 8; q++)
                CPA16(dsm + (tid*36 + q*4)*4, &BT[(size_t)tid*256 + (kc+1)*32 + q*4]);
            CPA_COMMIT();
        }
        unsigned int* Bcur = Bs + (kc & 1)*(256*36);
        #pragma unroll
        for (int ks = 0; ks < 4; ks++) {
            int pb = ks*8;
            unsigned int bf0[4], bf1[4];
            #pragma unroll
            for (int nt = 0; nt < 4; nt++) {
                int n = warp*32 + nt*8 + lane4;
                bf0[nt] = Bcur[n*36 + pb + lanem];
                bf1[nt] = Bcur[n*36 + pb + lanem + 4];
            }
            #pragma unroll
            for (int mt = 0; mt < 2; mt++) {
                int r = mt*16 + lane4;
                int kA = kc*32 + pb + lanem;
                unsigned int a0 = As[r*260 + kA];
                unsigned int a1 = As[(r+8)*260 + kA];
                unsigned int a2 = As[r*260 + kA + 4];
                unsigned int a3 = As[(r+8)*260 + kA + 4];
                #pragma unroll
                for (int nt = 0; nt < 4; nt++)
                    mma8(acc[mt][nt], a0, a1, a2, a3, bf0[nt], bf1[nt]);
            }
        }
        if (kc < 7) CPA_WAIT0();
        __syncthreads();
    }

    float* outp = half ? (set ? g_Q2 : g_Q) : (set ? g_P2 : g_P);
    #pragma unroll
    for (int mt = 0; mt < 2; mt++) {
        int r = mt*16 + lane4;
        #pragma unroll
        for (int nt = 0; nt < 4; nt++) {
            int n = warp*32 + nt*8 + lanem*2;
            float2 bb = half ? make_float2(0.f, 0.f) : *(const float2*)&b1[n];
            if (r0 + r < NROWS)
                *(float2*)&outp[(size_t)(r0+r)*HS + n] =
                    make_float2(acc[mt][nt][0] + bb.x, acc[mt][nt][1] + bb.y);
            if (r0 + r + 8 < NROWS)
                *(float2*)&outp[(size_t)(r0+r+8)*HS + n] =
                    make_float2(acc[mt][nt][2] + bb.x, acc[mt][nt][3] + bb.y);
        }
    }
}

// =====================================================================
// Node MLP via tf32 mma, fused 2 layers + residual, M=32, grid 88.
// =====================================================================
__global__ __launch_bounds__(256) void k_nodem(
    int m, const float* __restrict__ b1, const float* __restrict__ b2,
    const float* __restrict__ nm)
{
    extern __shared__ float S[];
    unsigned int* A1 = (unsigned int*)S;
    unsigned int* Bs = A1 + RPB*516;
    unsigned int* A2 = Bs + 2*256*36;
    const unsigned int* B1T = g_Wn1T + (size_t)m*131072;
    const unsigned int* B2T = g_Wn2T + (size_t)m*65536;
    uint32_t bsm = sptr(Bs);

    int tid = threadIdx.x, warp = tid >> 5, lane = tid & 31;
    int lane4 = lane >> 2, lanem = lane & 3;
    int r0 = blockIdx.x * RPB;

    #pragma unroll
    for (int q = 0; q < 8; q++)
        CPA16(bsm + (tid*36 + q*4)*4, &B1T[(size_t)tid*512 + q*4]);
    CPA_COMMIT();

    for (int idx = tid; idx < RPB*512; idx += 256) {
        int row = idx >> 9, k = idx & 511;
        float v = 0.f;
        int gr = r0 + row;
        if (gr < NROWS)
            v = (k < 256) ? g_h[(size_t)gr*HS + k] : g_agg[(size_t)gr*HS + (k-256)];
        A1[row*516 + k] = f2tf32(v);
    }
    CPA_WAIT0();
    __syncthreads();

    float acc[2][4][4];
    #pragma unroll
    for (int mt = 0; mt < 2; mt++)
        #pragma unroll
        for (int nt = 0; nt < 4; nt++)
            #pragma unroll
            for (int q = 0; q < 4; q++) acc[mt][nt][q] = 0.f;

    for (int kc = 0; kc < 16; kc++) {
        if (kc < 15) {
            uint32_t dsm = bsm + (((kc+1) & 1) ? 256*36*4 : 0);
            #pragma unroll
            for (int q = 0; q < 8; q++)
                CPA16(dsm + (tid*36 + q*4)*4, &B1T[(size_t)tid*512 + (kc+1)*32 + q*4]);
            CPA_COMMIT();
        }
        unsigned int* Bcur = Bs + (kc & 1)*(256*36);
        #pragma unroll
        for (int ks = 0; ks < 4; ks++) {
            int pb = ks*8;
            unsigned int bf0[4], bf1[4];
            #pragma unroll
            for (int nt = 0; nt < 4; nt++) {
                int n = warp*32 + nt*8 + lane4;
                bf0[nt] = Bcur[n*36 + pb + lanem];
                bf1[nt] = Bcur[n*36 + pb + lanem + 4];
            }
            #pragma unroll
            for (int mt = 0; mt < 2; mt++) {
                int r = mt*16 + lane4;
                int kA = kc*32 + pb + lanem;
                unsigned int a0 = A1[r*516 + kA];
                unsigned int a1 = A1[(r+8)*516 + kA];
                unsigned int a2 = A1[r*516 + kA + 4];
                unsigned int a3 = A1[(r+8)*516 + kA + 4];
                #pragma unroll
                for (int nt = 0; nt < 4; nt++)
                    mma8(acc[mt][nt], a0, a1, a2, a3, bf0[nt], bf1[nt]);
            }
        }
        if (kc < 15) CPA_WAIT0();
        __syncthreads();
    }

    #pragma unroll
    for (int q = 0; q < 8; q++)
        CPA16(bsm + (tid*36 + q*4)*4, &B2T[(size_t)tid*256 + q*4]);
    CPA_COMMIT();
    #pragma unroll
    for (int mt = 0; mt < 2; mt++) {
        int r = mt*16 + lane4;
        #pragma unroll
        for (int nt = 0; nt < 4; nt++) {
            int n = warp*32 + nt*8 + lanem*2;
            float2 bb = *(const float2*)&b1[n];
            A2[r*260 + n]       = f2tf32(silu_f(acc[mt][nt][0] + bb.x));
            A2[r*260 + n + 1]   = f2tf32(silu_f(acc[mt][nt][1] + bb.y));
            A2[(r+8)*260 + n]   = f2tf32(silu_f(acc[mt][nt][2] + bb.x));
            A2[(r+8)*260 + n+1] = f2tf32(silu_f(acc[mt][nt][3] + bb.y));
        }
    }
    #pragma unroll
    for (int mt = 0; mt < 2; mt++)
        #pragma unroll
        for (int nt = 0; nt < 4; nt++)
            #pragma unroll
            for (int q = 0; q < 4; q++) acc[mt][nt][q] = 0.f;
    CPA_WAIT0();
    __syncthreads();

    for (int kc = 0; kc < 8; kc++) {
        if (kc < 7) {
            uint32_t dsm = bsm + (((kc+1) & 1) ? 256*36*4 : 0);
            #pragma unroll
            for (int q = 0; q < 8; q++)
                CPA16(dsm + (tid*36 + q*4)*4, &B2T[(size_t)tid*256 + (kc+1)*32 + q*4]);
            CPA_COMMIT();
        }
        unsigned int* Bcur = Bs + (kc & 1)*(256*36);
        #pragma unroll
        for (int ks = 0; ks < 4; ks++) {
            int pb = ks*8;
            unsigned int bf0[4], bf1[4];
            #pragma unroll
            for (int nt = 0; nt < 4; nt++) {
                int n = warp*32 + nt*8 + lane4;
                bf0[nt] = Bcur[n*36 + pb + lanem];
                bf1[nt] = Bcur[n*36 + pb + lanem + 4];
            }
            #pragma unroll
            for (int mt = 0; mt < 2; mt++) {
                int r = mt*16 + lane4;
                int kA = kc*32 + pb + lanem;
                unsigned int a0 = A2[r*260 + kA];
                unsigned int a1 = A2[(r+8)*260 + kA];
                unsigned int a2 = A2[r*260 + kA + 4];
                unsigned int a3 = A2[(r+8)*260 + kA + 4];
                #pragma unroll
                for (int nt = 0; nt < 4; nt++)
                    mma8(acc[mt][nt], a0, a1, a2, a3, bf0[nt], bf1[nt]);
            }
        }
        if (kc < 7) CPA_WAIT0();
        __syncthreads();
    }

    #pragma unroll
    for (int mt = 0; mt < 2; mt++) {
        int r = mt*16 + lane4;
        #pragma unroll
        for (int nt = 0; nt < 4; nt++) {
            int n = warp*32 + nt*8 + lanem*2;
            float2 bb = *(const float2*)&b2[n];
            int gr = r0 + r;
            if (gr < NROWS) {
                float mk = nm[gr];
                float2 old = *(float2*)&g_h[(size_t)gr*HS + n];
                *(float2*)&g_h[(size_t)gr*HS + n] =
                    make_float2((old.x + bb.x + acc[mt][nt][0])*mk,
                                (old.y + bb.y + acc[mt][nt][1])*mk);
            }
            int gr2 = gr + 8;
            if (gr2 < NROWS) {
                float mk = nm[gr2];
                float2 old = *(float2*)&g_h[(size_t)gr2*HS + n];
                *(float2*)&g_h[(size_t)gr2*HS + n] =
                    make_float2((old.x + bb.x + acc[mt][nt][2])*mk,
                                (old.y + bb.y + acc[mt][nt][3])*mk);
            }
        }
    }
}

// =====================================================================
// k_init
// =====================================================================
__global__ __launch_bounds__(256) void k_init(
    const float* __restrict__ xh, const float* __restrict__ nm,
    const float* __restrict__ tt,
    const float* __restrict__ We, const float* __restrict__ be,
    const float* __restrict__ rep, const float* __restrict__ Wr,
    const float* __restrict__ br)
{
    __shared__ float sr[REPF];
    __shared__ float srp[HS];
    __shared__ float sf[NJ*8];
    __shared__ float sx[NJ*3];
    int b = blockIdx.x, c = threadIdx.x;
    sr[c]       = rep[b*REPF + c];
    sr[c + 256] = rep[b*REPF + 256 + c];
    __syncthreads();
    {
        float a0=0.f,a1=0.f,a2=0.f,a3=0.f;
        const float* w = Wr + c;
        #pragma unroll 4
        for (int k = 0; k < REPF; k += 4) {
            a0 += sr[k+0]*w[(k+0)*HS];
            a1 += sr[k+1]*w[(k+1)*HS];
            a2 += sr[k+2]*w[(k+2)*HS];
            a3 += sr[k+3]*w[(k+3)*HS];
        }
        srp[c] = br[c] + be[c] + ((a0+a1)+(a2+a3));
    }
    if (c < NJ) {
        float m = nm[b*NJ + c];
        const float* row = xh + (b*NJ + c)*9;
        #pragma unroll
        for (int d = 0; d < 3; d++) {
            float xv = row[d] * m;
            g_x0[(b*NJ+c)*3 + d] = xv;
            g_x [(b*NJ+c)*3 + d] = xv;
            sx[c*3 + d] = xv;
        }
        #pragma unroll
        for (int k = 0; k < 6; k++) sf[c*8 + k] = row[3+k] * m;
        sf[c*8 + 6] = tt[b];
    }
    __syncthreads();
    {
        float w[7];
        #pragma unroll
        for (int k = 0; k < 7; k++) w[k] = We[k*HS + c];
        for (int i = 0; i < NJ; i++) {
            float a = srp[c];
            #pragma unroll
            for (int k = 0; k < 7; k++) a += sf[i*8 + k] * w[k];
            g_h[(size_t)(b*NJ + i)*HS + c] = a;
        }
    }
    for (int idx = c; idx < NJ*NJ; idx += 256) {
        int i = idx / NJ, j = idx % NJ;
        float dx = sx[i*3+0]-sx[j*3+0];
        float dy = sx[i*3+1]-sx[j*3+1];
        float dz = sx[i*3+2]-sx[j*3+2];
        float r = dx*dx + dy*dy + dz*dz;
        g_d0[b*NJ*NJ + idx] = r;
        g_d [b*NJ*NJ + idx] = r;
        float inv = rsqrtf(r + 1e-8f);
        int o = (b*NJ*NJ + idx)*3;
        g_cdiff[o+0] = dx*inv;
        g_cdiff[o+1] = dy*inv;
        g_cdiff[o+2] = dz*inv;
    }
}

// ---------------- pairwise distances ----------------
__global__ __launch_bounds__(256) void k_dist() {
    __shared__ float sx[NJ*3];
    int b = blockIdx.x, t = threadIdx.x;
    if (t < NJ*3) sx[t] = g_x[b*NJ*3 + t];
    __syncthreads();
    for (int idx = t; idx < NJ*NJ; idx += 256) {
        int i = idx / NJ, j = idx % NJ;
        float dx = sx[i*3+0]-sx[j*3+0];
        float dy = sx[i*3+1]-sx[j*3+1];
        float dz = sx[i*3+2]-sx[j*3+2];
        float r = dx*dx + dy*dy + dz*dz;
        g_d[b*NJ*NJ + idx] = r;
        float inv = rsqrtf(r + 1e-8f);
        int o = (b*NJ*NJ + idx)*3;
        g_cdiff[o+0] = dx*inv;
        g_cdiff[o+1] = dy*inv;
        g_cdiff[o+2] = dz*inv;
    }
}

// ---------------- output head ----------------
__global__ __launch_bounds__(256) void k_out(const float* __restrict__ nm,
                                             const float* __restrict__ Wo,
                                             const float* __restrict__ bo,
                                             float* __restrict__ out) {
    int b = blockIdx.x, t = threadIdx.x;
    __shared__ float svel[NJ*3];
    __shared__ float smask[NJ];
    __shared__ float smean[3];
    if (t < NJ) {
        float m = nm[b*NJ + t];
        smask[t] = m;
        #pragma unroll
        for (int d = 0; d < 3; d++)
            svel[t*3+d] = (g_x[(b*NJ+t)*3+d] - g_x0[(b*NJ+t)*3+d]) * m;
    }
    __syncthreads();
    if (t == 0) {
        float s0=0.f,s1=0.f,s2=0.f,n=0.f;
        for (int j = 0; j < NJ; j++) {
            s0 += svel[j*3+0]; s1 += svel[j*3+1]; s2 += svel[j*3+2];
            n  += smask[j];
        }
        smean[0] = s0/n; smean[1] = s1/n; smean[2] = s2/n;
    }
    __syncthreads();
    if (t < NJ) {
        #pragma unroll
        for (int d = 0; d < 3; d++)
            out[(b*NJ+t)*9 + d] = (svel[t*3+d] - smean[d]) * smask[t];
    }
    int w = t >> 5, lane = t & 31;
    for (int i = w; i < NJ; i += 8) {
        float a0=0.f,a1=0.f,a2=0.f,a3=0.f,a4=0.f,a5=0.f;
        const float* hp = g_h + (size_t)(b*NJ + i)*HS;
        for (int k = lane; k < HS; k += 32) {
            float hv = hp[k];
            const float* wr = Wo + k*7;
            a0 += hv*wr[0]; a1 += hv*wr[1]; a2 += hv*wr[2];
            a3 += hv*wr[3]; a4 += hv*wr[4]; a5 += hv*wr[5];
        }
        #pragma unroll
        for (int off = 16; off > 0; off >>= 1) {
            a0 += __shfl_down_sync(0xffffffffu, a0, off);
            a1 += __shfl_down_sync(0xffffffffu, a1, off);
            a2 += __shfl_down_sync(0xffffffffu, a2, off);
            a3 += __shfl_down_sync(0xffffffffu, a3, off);
            a4 += __shfl_down_sync(0xffffffffu, a4, off);
            a5 += __shfl_down_sync(0xffffffffu, a5, off);
        }
        if (lane == 0) {
            float m = smask[i];
            float* o = out + (b*NJ+i)*9;
            o[3] = (a0 + bo[0]) * m;
            o[4] = (a1 + bo[1]) * m;
            o[5] = (a2 + bo[2]) * m;
            o[6] = (a3 + bo[3]) * m;
            o[7] = (a4 + bo[4]) * m;
            o[8] = (a5 + bo[5]) * m;
        }
    }
}

// ---------------- launch ----------------
extern "C" void kernel_launch(void* const* d_in, const int* in_sizes, int n_in,
                              void* d_out, int out_size) {
    (void)in_sizes; (void)n_in; (void)out_size;
    const float* t       = (const float*)d_in[0];
    const float* xh      = (const float*)d_in[1];
    const float* nm      = (const float*)d_in[2];
    const float* em      = (const float*)d_in[3];
    const float* rep     = (const float*)d_in[4];
    const float* W_embed = (const float*)d_in[5];
    const float* b_embed = (const float*)d_in[6];
    const float* W_rep   = (const float*)d_in[7];
    const float* b_rep   = (const float*)d_in[8];
    const float* We1     = (const float*)d_in[9];
    const float* be1     = (const float*)d_in[10];
    const float* We2     = (const float*)d_in[11];
    const float* be2     = (const float*)d_in[12];
    const float* Wn1     = (const float*)d_in[13];
    const float* bn1     = (const float*)d_in[14];
    const float* Wn2     = (const float*)d_in[15];
    const float* bn2     = (const float*)d_in[16];
    const float* Wc1     = (const float*)d_in[17];
    const float* bc1     = (const float*)d_in[18];
    const float* Wc2     = (const float*)d_in[19];
    const float* bc2     = (const float*)d_in[20];
    const float* Wc3     = (const float*)d_in[21];
    const float* W_out   = (const float*)d_in[22];
    const float* b_out   = (const float*)d_in[23];
    float* out = (float*)d_out;

    static bool attr_done = false;
    if (!attr_done) {
        cudaFuncSetAttribute(k_fused, cudaFuncAttributeMaxDynamicSharedMemorySize, FUSED_BYTES);
        cudaFuncSetAttribute(k_pqm,   cudaFuncAttributeMaxDynamicSharedMemorySize, PQM_BYTES);
        cudaFuncSetAttribute(k_nodem, cudaFuncAttributeMaxDynamicSharedMemorySize, NODEM_BYTES);
        attr_done = true;
    }

    k_prepall<<<dim3(8, 8, 60), dim3(32, 8)>>>(We2, Wc2, We1, Wc1, Wn1, Wn2);
    k_init<<<BSZ, 256>>>(xh, nm, t, W_embed, b_embed, rep, W_rep, b_rep);
    k_pqm<<<dim3(GBLK, 2, 1), 256, PQM_BYTES>>>(0, be1, -1, nullptr);

    int k = 0;
    for (int l = 0; l < NLAY; l++) {
        if (l > 0) k_dist<<<BSZ, 256>>>();
        k_fused<<<BSZ*22, 256, FUSED_BYTES>>>(We1 + (size_t)k*514*HS, k,
                                              be2 + k*HS, em, nullptr, nullptr, 0,
                                              (l > 0) ? 1 : 0);
        k_nodem<<<GBLK, 256, NODEM_BYTES>>>(k, bn1 + k*HS, bn2 + k*HS, nm);
        k_pqm<<<dim3(GBLK, 2, 1), 256, PQM_BYTES>>>(k + 1, be1 + (size_t)(k+1)*HS,
                                                    -1, nullptr);
        k++;
        k_fused<<<BSZ*22, 256, FUSED_BYTES>>>(We1 + (size_t)k*514*HS, k,
                                              be2 + k*HS, em, nullptr, nullptr, 0, 0);
        k_nodem<<<GBLK, 256, NODEM_BYTES>>>(k, bn1 + k*HS, bn2 + k*HS, nm);
        if (l < NLAY - 1) {
            k_pqm<<<dim3(GBLK, 2, 2), 256, PQM_BYTES>>>(8 + l, bc1 + (size_t)l*HS,
                                                        k + 1, be1 + (size_t)(k+1)*HS);
        } else {
            k_pqm<<<dim3(GBLK, 2, 1), 256, PQM_BYTES>>>(8 + l, bc1 + (size_t)l*HS,
                                                        -1, nullptr);
        }
        k++;
        k_fused<<<BSZ*22, 256, FUSED_BYTES>>>(Wc1 + (size_t)l*514*HS, 8 + l,
                                              bc2 + l*HS, em, Wc3 + (size_t)l*HS, nm, 1, 0);
    }
    k_out<<<BSZ, 256>>>(nm, W_out, b_out, out);
}

// round 14
// speedup vs baseline: 1.1430x; 1.1430x over previous
#include <cuda_runtime.h>
#include <cuda_bf16.h>
#include <cstdint>

#define BSZ 64
#define NJ  44
#define HS  256
#define REPF 512
#define NLAY 4
#define NROWS (BSZ*NJ)
#define RPB 32
#define GBLK 88

// ---------------- persistent device state ----------------
__device__ float g_h[NROWS*HS];
__device__ float g_agg[NROWS*HS];
__device__ float g_P[NROWS*HS];
__device__ float g_Q[NROWS*HS];
__device__ float g_P2[NROWS*HS];
__device__ float g_Q2[NROWS*HS];
__device__ float g_x[NROWS*3];
__device__ float g_x0[NROWS*3];
__device__ float g_d[BSZ*NJ*NJ];
__device__ float g_d0[BSZ*NJ*NJ];
__device__ float g_cdiff[BSZ*NJ*NJ*3];
__device__ unsigned int g_W2T [12*256*128];     // bf16x2 [m][n][kpair]
__device__ unsigned int g_WpqT[12*2*256*256];   // tf32 [m][half][n][k]
__device__ unsigned int g_Wn1T[8*256*512];      // tf32 [m][n][k]
__device__ unsigned int g_Wn2T[8*256*256];      // tf32 [m][n][k]

__device__ __forceinline__ float silu_f(float x) {
    return x / (1.0f + __expf(-x));
}
__device__ __forceinline__ float silu_t(float x) {
    float t;
    asm("tanh.approx.f32 %0, %1;" : "=f"(t) : "f"(0.5f*x));
    return 0.5f*x*(1.0f + t);
}
__device__ __forceinline__ unsigned int packbf(float lo, float hi) {
    __nv_bfloat162 h2 = __floats2bfloat162_rn(lo, hi);
    return *(unsigned int*)&h2;
}
__device__ __forceinline__ unsigned int f2tf32(float v) {
    unsigned int u;
    asm("cvt.rna.tf32.f32 %0, %1;" : "=r"(u) : "f"(v));
    return u;
}
__device__ __forceinline__ uint32_t sptr(const void* p) {
    uint32_t a;
    asm("{ .reg .u64 t; cvta.to.shared.u64 t, %1; cvt.u32.u64 %0, t; }" : "=r"(a) : "l"(p));
    return a;
}
__device__ __forceinline__ void mma16(float c[4], unsigned a0, unsigned a1,
                                      unsigned a2, unsigned a3,
                                      unsigned b0, unsigned b1) {
    asm volatile("mma.sync.aligned.m16n8k16.row.col.f32.bf16.bf16.f32 "
        "{%0,%1,%2,%3}, {%4,%5,%6,%7}, {%8,%9}, {%0,%1,%2,%3};"
        : "+f"(c[0]), "+f"(c[1]), "+f"(c[2]), "+f"(c[3])
        : "r"(a0), "r"(a1), "r"(a2), "r"(a3), "r"(b0), "r"(b1));
}
__device__ __forceinline__ void mma8(float c[4], unsigned a0, unsigned a1,
                                     unsigned a2, unsigned a3,
                                     unsigned b0, unsigned b1) {
    asm volatile("mma.sync.aligned.m16n8k8.row.col.f32.tf32.tf32.f32 "
        "{%0,%1,%2,%3}, {%4,%5,%6,%7}, {%8,%9}, {%0,%1,%2,%3};"
        : "+f"(c[0]), "+f"(c[1]), "+f"(c[2]), "+f"(c[3])
        : "r"(a0), "r"(a1), "r"(a2), "r"(a3), "r"(b0), "r"(b1));
}
#define LDSM4(r0, r1, r2, r3, addr) \
    asm volatile("ldmatrix.sync.aligned.m8n8.x4.shared.b16 {%0,%1,%2,%3}, [%4];" \
        : "=r"(r0), "=r"(r1), "=r"(r2), "=r"(r3) : "r"(addr))
#define CPA16(dst, src) asm volatile("cp.async.cg.shared.global [%0], [%1], 16;" :: "r"(dst), "l"(src) : "memory")
#define CPA_COMMIT()    asm volatile("cp.async.commit_group;" ::: "memory")
#define CPA_WAIT0()     asm volatile("cp.async.wait_group 0;" ::: "memory")

// ---------------- weight prep (all transposes in one kernel) ----------------
__global__ void k_prepall(const float* __restrict__ We2, const float* __restrict__ Wc2,
                          const float* __restrict__ We1, const float* __restrict__ Wc1,
                          const float* __restrict__ Wn1, const float* __restrict__ Wn2) {
    __shared__ float tile[32][33];
    int z = blockIdx.z;
    int k0 = blockIdx.x*32, n0 = blockIdx.y*32;
    int tx = threadIdx.x, ty = threadIdx.y;
    int tid = ty*32 + tx;
    if (z < 12) {
        int m = z;
        const float* src = (m < 8) ? We2 + (size_t)m*HS*HS : Wc2 + (size_t)(m-8)*HS*HS;
        unsigned int* dst = g_W2T + (size_t)m*256*128;
        #pragma unroll
        for (int q = 0; q < 4; q++)
            tile[ty + 8*q][tx] = src[(size_t)(k0 + ty + 8*q)*HS + n0 + tx];
        __syncthreads();
        for (int o = tid; o < 512; o += 256) {
            int nl = o >> 4, p = o & 15;
            dst[(size_t)(n0 + nl)*128 + (k0 >> 1) + p] = packbf(tile[2*p][nl], tile[2*p+1][nl]);
        }
        return;
    }
    int v = z - 12;
    const float* src; unsigned int* dst; int stride, koff;
    if (v < 24) {
        int m = v >> 1, half = v & 1;
        src = ((m < 8) ? We1 + (size_t)m*514*HS : Wc1 + (size_t)(m-8)*514*HS)
              + (size_t)half*HS*HS;
        dst = g_WpqT + ((size_t)m*2 + half)*65536; stride = 256; koff = 0;
    } else if (v < 40) {
        int u = v - 24, m = u >> 1, kh = u & 1;
        src = Wn1 + (size_t)m*512*HS + (size_t)kh*HS*HS;
        dst = g_Wn1T + (size_t)m*131072; stride = 512; koff = kh*256;
    } else {
        int m = v - 40;
        src = Wn2 + (size_t)m*HS*HS;
        dst = g_Wn2T + (size_t)m*65536; stride = 256; koff = 0;
    }
    #pragma unroll
    for (int q = 0; q < 4; q++)
        tile[ty + 8*q][tx] = src[(size_t)(k0 + ty + 8*q)*HS + n0 + tx];
    __syncthreads();
    for (int o = tid; o < 1024; o += 256) {
        int nl = o >> 5, kk = o & 31;
        dst[(size_t)(n0 + nl)*stride + koff + k0 + kk] = f2tf32(tile[kk][nl]);
    }
}

// ---------------- k_fused smem layout (M=96: 2 edges/block) ----------------
#define F_OD   22912
#define F_OD0  23008
#define F_OMK  23104
#define F_OPS  23200
#define F_OPHI 23968
#define FUSED_FLOATS 24064
#define FUSED_BYTES (FUSED_FLOATS*4)
#define PQM_BYTES   ((RPB*260 + 2*256*36)*4)
#define NODEM_BYTES ((RPB*516 + 2*256*36 + RPB*260)*4)

// =====================================================================
// Fused edge/coord MLP; block = (b, i-pair): M=96 rows, N=256.
// =====================================================================
__global__ __launch_bounds__(256, 2) void k_fused(
    const float* __restrict__ W1,
    int mW2,
    const float* __restrict__ b2,
    const float* __restrict__ em,
    const float* __restrict__ W3,
    const float* __restrict__ nm,
    int mode, int pqbuf)
{
    extern __shared__ float S[];
    unsigned int* As = (unsigned int*)S;           // [96][132]
    unsigned int* Bs = As + 96*132;                // 2 x [256][20]
    const unsigned int* W2T = g_W2T + (size_t)mW2*256*128;
    const float* Pp = pqbuf ? g_P2 : g_P;
    const float* Qp = pqbuf ? g_Q2 : g_Q;

    int tid = threadIdx.x, warp = tid >> 5, lane = tid & 31;
    int lane4 = lane >> 2, lanem = lane & 3;
    int b = blockIdx.x / 22, pr = blockIdx.x % 22;
    int i0 = 2*pr;
    uint32_t bsm = sptr(Bs);
    uint32_t asmb = sptr(As);
    int cn = tid >> 2, cq = (tid & 3)*4;

    #pragma unroll
    for (int r = 0; r < 4; r++) {
        int nr = cn + r*64;
        CPA16(bsm + (nr*20 + cq)*4, &W2T[(size_t)nr*128 + cq]);
    }
    CPA_COMMIT();

    if (tid < 96) {
        int g = tid / 48, j = tid % 48;
        float dv = 0.f, d0v = 0.f, mv = 0.f;
        if (j < NJ) {
            int e = (b*NJ + i0 + g)*NJ + j;
            dv = g_d[e]; d0v = g_d0[e]; mv = em[e];
        }
        S[F_OD + tid] = dv; S[F_OD0 + tid] = d0v; S[F_OMK + tid] = mv;
    }
    __syncthreads();

    // ---- phase 1 ----
    {
        int cp = tid & 127, jh = tid >> 7;
        float2 Pv0 = *(const float2*)&Pp[(size_t)(b*NJ + i0    )*HS + 2*cp];
        float2 Pv1 = *(const float2*)&Pp[(size_t)(b*NJ + i0 + 1)*HS + 2*cp];
        float2 wdv = *(const float2*)&W1[512*HS + 2*cp];
        float2 wd0v= *(const float2*)&W1[513*HS + 2*cp];
        const float* qbase = Qp + (size_t)b*NJ*HS + 2*cp;
        int j0 = jh * 22;
        #pragma unroll
        for (int batch = 0; batch < 2; batch++) {
            float2 qv[11];
            #pragma unroll
            for (int u = 0; u < 11; u++)
                qv[u] = *(const float2*)&qbase[(size_t)(j0 + batch*11 + u)*HS];
            #pragma unroll
            for (int u = 0; u < 11; u++) {
                int j = j0 + batch*11 + u;
                float dj0 = S[F_OD + j],      d0j0 = S[F_OD0 + j];
                float dj1 = S[F_OD + 48 + j], d0j1 = S[F_OD0 + 48 + j];
                float base0 = qv[u].x, base1 = qv[u].y;
                float v00 = Pv0.x + base0 + wdv.x*dj0 + wd0v.x*d0j0;
                float v01 = Pv0.y + base1 + wdv.y*dj0 + wd0v.y*d0j0;
                float v10 = Pv1.x + base0 + wdv.x*dj1 + wd0v.x*d0j1;
                float v11 = Pv1.y + base1 + wdv.y*dj1 + wd0v.y*d0j1;
                As[j*132 + cp]        = packbf(silu_t(v00), silu_t(v01));
                As[(48 + j)*132 + cp] = packbf(silu_t(v10), silu_t(v11));
            }
        }
        for (int p = tid; p < 4*132; p += 256) {
            As[44*132 + p] = 0u;
            As[92*132 + p] = 0u;
        }
    }
    CPA_WAIT0();
    __syncthreads();

    // ---- phase 2 ----
    float acc[6][4][4];
    #pragma unroll
    for (int mt = 0; mt < 6; mt++)
        #pragma unroll
        for (int nt = 0; nt < 4; nt++)
            #pragma unroll
            for (int q = 0; q < 4; q++) acc[mt][nt][q] = 0.f;

    int l7 = lane & 7, sel = lane >> 3;
    uint32_t abase = asmb + ((((sel & 1)*8 + l7)*132) + (sel >> 1)*4)*4;
    uint32_t baddr[2];
    #pragma unroll
    for (int t = 0; t < 2; t++)
        baddr[t] = bsm + (((warp*32 + t*16 + (sel >> 1)*8 + l7)*20) + (sel & 1)*4)*4;

    for (int kc = 0; kc < 8; kc++) {
        if (kc < 7) {
            uint32_t dsm = bsm + (((kc+1) & 1) ? 256*20*4 : 0);
            #pragma unroll
            for (int r = 0; r < 4; r++) {
                int nr = cn + r*64;
                CPA16(dsm + (nr*20 + cq)*4, &W2T[(size_t)nr*128 + (kc+1)*16 + cq]);
            }
            CPA_COMMIT();
        }
        uint32_t boff = (kc & 1) ? 256*20*4 : 0;
        #pragma unroll
        for (int s = 0; s < 2; s++) {
            uint32_t koff = (uint32_t)(kc*16 + s*8)*4;
            unsigned int bb[8];
            LDSM4(bb[0], bb[1], bb[2], bb[3], baddr[0] + boff + s*8*4);
            LDSM4(bb[4], bb[5], bb[6], bb[7], baddr[1] + boff + s*8*4);
            #pragma unroll
            for (int mt = 0; mt < 6; mt++) {
                unsigned int a0, a1, a2, a3;
                LDSM4(a0, a1, a2, a3, abase + (uint32_t)mt*16*132*4 + koff);
                mma16(acc[mt][0], a0, a1, a2, a3, bb[0], bb[1]);
                mma16(acc[mt][1], a0, a1, a2, a3, bb[2], bb[3]);
                mma16(acc[mt][2], a0, a1, a2, a3, bb[4], bb[5]);
                mma16(acc[mt][3], a0, a1, a2, a3, bb[6], bb[7]);
            }
        }
        if (kc < 7) CPA_WAIT0();
        __syncthreads();
    }

    // ---- epilogue ----
    float msk[12];
    #pragma unroll
    for (int mt = 0; mt < 6; mt++) {
        msk[2*mt]   = S[F_OMK + mt*16 + lane4];
        msk[2*mt+1] = S[F_OMK + mt*16 + lane4 + 8];
    }
    if (mode == 0) {
        #pragma unroll
        for (int g = 0; g < 2; g++) {
            size_t rowbase = (size_t)(b*NJ + i0 + g)*HS;
            #pragma unroll
            for (int nt = 0; nt < 4; nt++) {
                int n = warp*32 + nt*8 + lanem*2;
                float2 bb = *(const float2*)&b2[n];
                float s0 = 0.f, s1 = 0.f;
                #pragma unroll
                for (int mm = 0; mm < 3; mm++) {
                    int mt = g*3 + mm;
                    s0 += silu_t(acc[mt][nt][0] + bb.x)*msk[2*mt]
                        + silu_t(acc[mt][nt][2] + bb.x)*msk[2*mt+1];
                    s1 += silu_t(acc[mt][nt][1] + bb.y)*msk[2*mt]
                        + silu_t(acc[mt][nt][3] + bb.y)*msk[2*mt+1];
                }
                #pragma unroll
                for (int off = 4; off <= 16; off <<= 1) {
                    s0 += __shfl_xor_sync(0xffffffffu, s0, off);
                    s1 += __shfl_xor_sync(0xffffffffu, s1, off);
                }
                if (lane4 == 0)
                    *(float2*)&g_agg[rowbase + n] = make_float2(s0*0.01f, s1*0.01f);
            }
        }
    } else {
        float ph[12];
        #pragma unroll
        for (int q = 0; q < 12; q++) ph[q] = 0.f;
        #pragma unroll
        for (int nt = 0; nt < 4; nt++) {
            int n = warp*32 + nt*8 + lanem*2;
            float2 bb = *(const float2*)&b2[n];
            float2 w3 = *(const float2*)&W3[n];
            #pragma unroll
            for (int mt = 0; mt < 6; mt++) {
                ph[2*mt]   += silu_t(acc[mt][nt][0] + bb.x)*w3.x
                            + silu_t(acc[mt][nt][1] + bb.y)*w3.y;
                ph[2*mt+1] += silu_t(acc[mt][nt][2] + bb.x)*w3.x
                            + silu_t(acc[mt][nt][3] + bb.y)*w3.y;
            }
        }
        #pragma unroll
        for (int q = 0; q < 12; q++) {
            ph[q] += __shfl_xor_sync(0xffffffffu, ph[q], 1);
            ph[q] += __shfl_xor_sync(0xffffffffu, ph[q], 2);
        }
        if (lanem == 0) {
            #pragma unroll
            for (int mt = 0; mt < 6; mt++) {
                S[F_OPS + warp*96 + mt*16 + lane4]     = ph[2*mt];
                S[F_OPS + warp*96 + mt*16 + lane4 + 8] = ph[2*mt+1];
            }
        }
        __syncthreads();
        if (tid < 96) {
            float p = 0.f;
            #pragma unroll
            for (int w = 0; w < 8; w++) p += S[F_OPS + w*96 + tid];
            S[F_OPHI + tid] = p * S[F_OMK + tid];
        }
        __syncthreads();
        // parallel trans reduction: 6 (g,d) pairs x 8 threads each
        if (tid < 48) {
            int pair = tid >> 3, t8 = tid & 7;
            int g = pair / 3, d = pair % 3;
            int i = i0 + g;
            const float* cd = g_cdiff + ((size_t)((b*NJ + i)*NJ))*3 + d;
            float s = 0.f;
            for (int j = t8; j < NJ; j += 8)
                s += cd[j*3] * S[F_OPHI + g*48 + j];
            s += __shfl_down_sync(0x0000ffffu >> (8*(pair & 1)) << (8*(pair & 1)) | 0xffffffffu, s, 4);
            s += __shfl_down_sync(0xffffffffu, s, 2);
            s += __shfl_down_sync(0xffffffffu, s, 1);
            if (t8 == 0) {
                float m = nm[b*NJ + i];
                int xi = (b*NJ + i)*3 + d;
                g_x[xi] = (g_x[xi] + s*0.01f) * m;
            }
        }
    }
}

// =====================================================================
// P/Q projection via tf32 mma, M=32/block, grid (88, 2, nsets).
// =====================================================================
__global__ __launch_bounds__(256) void k_pqm(
    int mWA, const float* __restrict__ bA,
    int mWB, const float* __restrict__ bB)
{
    extern __shared__ float S[];
    unsigned int* As = (unsigned int*)S;
    unsigned int* Bs = As + RPB*260;
    int tid = threadIdx.x, warp = tid >> 5, lane = tid & 31;
    int lane4 = lane >> 2, lanem = lane & 3;
    int r0 = blockIdx.x * RPB, half = blockIdx.y, set = blockIdx.z;
    int mW = set ? mWB : mWA;
    const float* b1 = set ? bB : bA;
    const unsigned int* BT = g_WpqT + ((size_t)mW*2 + half)*65536;
    uint32_t bsm = sptr(Bs);

    #pragma unroll
    for (int q = 0; q < 8; q++)
        CPA16(bsm + (tid*36 + q*4)*4, &BT[(size_t)tid*256 + q*4]);
    CPA_COMMIT();

    for (int idx = tid; idx < RPB*256; idx += 256) {
        int row = idx >> 8, k = idx & 255;
        float v = 0.f;
        int gr = r0 + row;
        if (gr < NROWS) v = g_h[(size_t)gr*HS + k];
        As[row*260 + k] = f2tf32(v);
    }
    CPA_WAIT0();
    __syncthreads();

    float acc[2][4][4];
    #pragma unroll
    for (int mt = 0; mt < 2; mt++)
        #pragma unroll
        for (int nt = 0; nt < 4; nt++)
            #pragma unroll
            for (int q = 0; q < 4; q++) acc[mt][nt][q] = 0.f;

    for (int kc = 0; kc < 8; kc++) {
        if (kc < 7) {
            uint32_t dsm = bsm + (((kc+1) & 1) ? 256*36*4 : 0);
            #pragma unroll
            for (int q = 0; q < 8; q++)
                CPA16(dsm + (tid*36 + q*4)*4, &BT[(size_t)tid*256 + (kc+1)*32 + q*4]);
            CPA_COMMIT();
        }
        unsigned int* Bcur = Bs + (kc & 1)*(256*36);
        #pragma unroll
        for (int ks = 0; ks < 4; ks++) {
            int pb = ks*8;
            unsigned int bf0[4], bf1[4];
            #pragma unroll
            for (int nt = 0; nt < 4; nt++) {
                int n = warp*32 + nt*8 + lane4;
                bf0[nt] = Bcur[n*36 + pb + lanem];
                bf1[nt] = Bcur[n*36 + pb + lanem + 4];
            }
            #pragma unroll
            for (int mt = 0; mt < 2; mt++) {
                int r = mt*16 + lane4;
                int kA = kc*32 + pb + lanem;
                unsigned int a0 = As[r*260 + kA];
                unsigned int a1 = As[(r+8)*260 + kA];
                unsigned int a2 = As[r*260 + kA + 4];
                unsigned int a3 = As[(r+8)*260 + kA + 4];
                #pragma unroll
                for (int nt = 0; nt < 4; nt++)
                    mma8(acc[mt][nt], a0, a1, a2, a3, bf0[nt], bf1[nt]);
            }
        }
        if (kc < 7) CPA_WAIT0();
        __syncthreads();
    }

    float* outp = half ? (set ? g_Q2 : g_Q) : (set ? g_P2 : g_P);
    #pragma unroll
    for (int mt = 0; mt < 2; mt++) {
        int r = mt*16 + lane4;
        #pragma unroll
        for (int nt = 0; nt < 4; nt++) {
            int n = warp*32 + nt*8 + lanem*2;
            float2 bb = half ? make_float2(0.f, 0.f) : *(const float2*)&b1[n];
            if (r0 + r < NROWS)
                *(float2*)&outp[(size_t)(r0+r)*HS + n] =
                    make_float2(acc[mt][nt][0] + bb.x, acc[mt][nt][1] + bb.y);
            if (r0 + r + 8 < NROWS)
                *(float2*)&outp[(size_t)(r0+r+8)*HS + n] =
                    make_float2(acc[mt][nt][2] + bb.x, acc[mt][nt][3] + bb.y);
        }
    }
}

// =====================================================================
// Node MLP via tf32 mma, fused 2 layers + residual, M=32, grid 88.
// =====================================================================
__global__ __launch_bounds__(256) void k_nodem(
    int m, const float* __restrict__ b1, const float* __restrict__ b2,
    const float* __restrict__ nm)
{
    extern __shared__ float S[];
    unsigned int* A1 = (unsigned int*)S;
    unsigned int* Bs = A1 + RPB*516;
    unsigned int* A2 = Bs + 2*256*36;
    const unsigned int* B1T = g_Wn1T + (size_t)m*131072;
    const unsigned int* B2T = g_Wn2T + (size_t)m*65536;
    uint32_t bsm = sptr(Bs);

    int tid = threadIdx.x, warp = tid >> 5, lane = tid & 31;
    int lane4 = lane >> 2, lanem = lane & 3;
    int r0 = blockIdx.x * RPB;

    #pragma unroll
    for (int q = 0; q < 8; q++)
        CPA16(bsm + (tid*36 + q*4)*4, &B1T[(size_t)tid*512 + q*4]);
    CPA_COMMIT();

    for (int idx = tid; idx < RPB*512; idx += 256) {
        int row = idx >> 9, k = idx & 511;
        float v = 0.f;
        int gr = r0 + row;
        if (gr < NROWS)
            v = (k < 256) ? g_h[(size_t)gr*HS + k] : g_agg[(size_t)gr*HS + (k-256)];
        A1[row*516 + k] = f2tf32(v);
    }
    CPA_WAIT0();
    __syncthreads();

    float acc[2][4][4];
    #pragma unroll
    for (int mt = 0; mt < 2; mt++)
        #pragma unroll
        for (int nt = 0; nt < 4; nt++)
            #pragma unroll
            for (int q = 0; q < 4; q++) acc[mt][nt][q] = 0.f;

    for (int kc = 0; kc < 16; kc++) {
        if (kc < 15) {
            uint32_t dsm = bsm + (((kc+1) & 1) ? 256*36*4 : 0);
            #pragma unroll
            for (int q = 0; q < 8; q++)
                CPA16(dsm + (tid*36 + q*4)*4, &B1T[(size_t)tid*512 + (kc+1)*32 + q*4]);
            CPA_COMMIT();
        }
        unsigned int* Bcur = Bs + (kc & 1)*(256*36);
        #pragma unroll
        for (int ks = 0; ks < 4; ks++) {
            int pb = ks*8;
            unsigned int bf0[4], bf1[4];
            #pragma unroll
            for (int nt = 0; nt < 4; nt++) {
                int n = warp*32 + nt*8 + lane4;
                bf0[nt] = Bcur[n*36 + pb + lanem];
                bf1[nt] = Bcur[n*36 + pb + lanem + 4];
            }
            #pragma unroll
            for (int mt = 0; mt < 2; mt++) {
                int r = mt*16 + lane4;
                int kA = kc*32 + pb + lanem;
                unsigned int a0 = A1[r*516 + kA];
                unsigned int a1 = A1[(r+8)*516 + kA];
                unsigned int a2 = A1[r*516 + kA + 4];
                unsigned int a3 = A1[(r+8)*516 + kA + 4];
                #pragma unroll
                for (int nt = 0; nt < 4; nt++)
                    mma8(acc[mt][nt], a0, a1, a2, a3, bf0[nt], bf1[nt]);
            }
        }
        if (kc < 15) CPA_WAIT0();
        __syncthreads();
    }

    #pragma unroll
    for (int q = 0; q < 8; q++)
        CPA16(bsm + (tid*36 + q*4)*4, &B2T[(size_t)tid*256 + q*4]);
    CPA_COMMIT();
    #pragma unroll
    for (int mt = 0; mt < 2; mt++) {
        int r = mt*16 + lane4;
        #pragma unroll
        for (int nt = 0; nt < 4; nt++) {
            int n = warp*32 + nt*8 + lanem*2;
            float2 bb = *(const float2*)&b1[n];
            A2[r*260 + n]       = f2tf32(silu_f(acc[mt][nt][0] + bb.x));
            A2[r*260 + n + 1]   = f2tf32(silu_f(acc[mt][nt][1] + bb.y));
            A2[(r+8)*260 + n]   = f2tf32(silu_f(acc[mt][nt][2] + bb.x));
            A2[(r+8)*260 + n+1] = f2tf32(silu_f(acc[mt][nt][3] + bb.y));
        }
    }
    #pragma unroll
    for (int mt = 0; mt < 2; mt++)
        #pragma unroll
        for (int nt = 0; nt < 4; nt++)
            #pragma unroll
            for (int q = 0; q < 4; q++) acc[mt][nt][q] = 0.f;
    CPA_WAIT0();
    __syncthreads();

    for (int kc = 0; kc < 8; kc++) {
        if (kc < 7) {
            uint32_t dsm = bsm + (((kc+1) & 1) ? 256*36*4 : 0);
            #pragma unroll
            for (int q = 0; q < 8; q++)
                CPA16(dsm + (tid*36 + q*4)*4, &B2T[(size_t)tid*256 + (kc+1)*32 + q*4]);
            CPA_COMMIT();
        }
        unsigned int* Bcur = Bs + (kc & 1)*(256*36);
        #pragma unroll
        for (int ks = 0; ks < 4; ks++) {
            int pb = ks*8;
            unsigned int bf0[4], bf1[4];
            #pragma unroll
            for (int nt = 0; nt < 4; nt++) {
                int n = warp*32 + nt*8 + lane4;
                bf0[nt] = Bcur[n*36 + pb + lanem];
                bf1[nt] = Bcur[n*36 + pb + lanem + 4];
            }
            #pragma unroll
            for (int mt = 0; mt < 2; mt++) {
                int r = mt*16 + lane4;
                int kA = kc*32 + pb + lanem;
                unsigned int a0 = A2[r*260 + kA];
                unsigned int a1 = A2[(r+8)*260 + kA];
                unsigned int a2 = A2[r*260 + kA + 4];
                unsigned int a3 = A2[(r+8)*260 + kA + 4];
                #pragma unroll
                for (int nt = 0; nt < 4; nt++)
                    mma8(acc[mt][nt], a0, a1, a2, a3, bf0[nt], bf1[nt]);
            }
        }
        if (kc < 7) CPA_WAIT0();
        __syncthreads();
    }

    #pragma unroll
    for (int mt = 0; mt < 2; mt++) {
        int r = mt*16 + lane4;
        #pragma unroll
        for (int nt = 0; nt < 4; nt++) {
            int n = warp*32 + nt*8 + lanem*2;
            float2 bb = *(const float2*)&b2[n];
            int gr = r0 + r;
            if (gr < NROWS) {
                float mk = nm[gr];
                float2 old = *(float2*)&g_h[(size_t)gr*HS + n];
                *(float2*)&g_h[(size_t)gr*HS + n] =
                    make_float2((old.x + bb.x + acc[mt][nt][0])*mk,
                                (old.y + bb.y + acc[mt][nt][1])*mk);
            }
            int gr2 = gr + 8;
            if (gr2 < NROWS) {
                float mk = nm[gr2];
                float2 old = *(float2*)&g_h[(size_t)gr2*HS + n];
                *(float2*)&g_h[(size_t)gr2*HS + n] =
                    make_float2((old.x + bb.x + acc[mt][nt][2])*mk,
                                (old.y + bb.y + acc[mt][nt][3])*mk);
            }
        }
    }
}

// =====================================================================
// k_init
// =====================================================================
__global__ __launch_bounds__(256) void k_init(
    const float* __restrict__ xh, const float* __restrict__ nm,
    const float* __restrict__ tt,
    const float* __restrict__ We, const float* __restrict__ be,
    const float* __restrict__ rep, const float* __restrict__ Wr,
    const float* __restrict__ br)
{
    __shared__ float sr[REPF];
    __shared__ float srp[HS];
    __shared__ float sf[NJ*8];
    __shared__ float sx[NJ*3];
    int b = blockIdx.x, c = threadIdx.x;
    sr[c]       = rep[b*REPF + c];
    sr[c + 256] = rep[b*REPF + 256 + c];
    __syncthreads();
    {
        float a0=0.f,a1=0.f,a2=0.f,a3=0.f;
        const float* w = Wr + c;
        #pragma unroll 4
        for (int k = 0; k < REPF; k += 4) {
            a0 += sr[k+0]*w[(k+0)*HS];
            a1 += sr[k+1]*w[(k+1)*HS];
            a2 += sr[k+2]*w[(k+2)*HS];
            a3 += sr[k+3]*w[(k+3)*HS];
        }
        srp[c] = br[c] + be[c] + ((a0+a1)+(a2+a3));
    }
    if (c < NJ) {
        float m = nm[b*NJ + c];
        const float* row = xh + (b*NJ + c)*9;
        #pragma unroll
        for (int d = 0; d < 3; d++) {
            float xv = row[d] * m;
            g_x0[(b*NJ+c)*3 + d] = xv;
            g_x [(b*NJ+c)*3 + d] = xv;
            sx[c*3 + d] = xv;
        }
        #pragma unroll
        for (int k = 0; k < 6; k++) sf[c*8 + k] = row[3+k] * m;
        sf[c*8 + 6] = tt[b];
    }
    __syncthreads();
    {
        float w[7];
        #pragma unroll
        for (int k = 0; k < 7; k++) w[k] = We[k*HS + c];
        for (int i = 0; i < NJ; i++) {
            float a = srp[c];
            #pragma unroll
            for (int k = 0; k < 7; k++) a += sf[i*8 + k] * w[k];
            g_h[(size_t)(b*NJ + i)*HS + c] = a;
        }
    }
    for (int idx = c; idx < NJ*NJ; idx += 256) {
        int i = idx / NJ, j = idx % NJ;
        float dx = sx[i*3+0]-sx[j*3+0];
        float dy = sx[i*3+1]-sx[j*3+1];
        float dz = sx[i*3+2]-sx[j*3+2];
        float r = dx*dx + dy*dy + dz*dz;
        g_d0[b*NJ*NJ + idx] = r;
        g_d [b*NJ*NJ + idx] = r;
        float inv = rsqrtf(r + 1e-8f);
        int o = (b*NJ*NJ + idx)*3;
        g_cdiff[o+0] = dx*inv;
        g_cdiff[o+1] = dy*inv;
        g_cdiff[o+2] = dz*inv;
    }
}

// ---------------- pairwise distances ----------------
__global__ __launch_bounds__(256) void k_dist() {
    __shared__ float sx[NJ*3];
    int b = blockIdx.x, t = threadIdx.x;
    if (t < NJ*3) sx[t] = g_x[b*NJ*3 + t];
    __syncthreads();
    for (int idx = t; idx < NJ*NJ; idx += 256) {
        int i = idx / NJ, j = idx % NJ;
        float dx = sx[i*3+0]-sx[j*3+0];
        float dy = sx[i*3+1]-sx[j*3+1];
        float dz = sx[i*3+2]-sx[j*3+2];
        float r = dx*dx + dy*dy + dz*dz;
        g_d[b*NJ*NJ + idx] = r;
        float inv = rsqrtf(r + 1e-8f);
        int o = (b*NJ*NJ + idx)*3;
        g_cdiff[o+0] = dx*inv;
        g_cdiff[o+1] = dy*inv;
        g_cdiff[o+2] = dz*inv;
    }
}

// ---------------- output head ----------------
__global__ __launch_bounds__(256) void k_out(const float* __restrict__ nm,
                                             const float* __restrict__ Wo,
                                             const float* __restrict__ bo,
                                             float* __restrict__ out) {
    int b = blockIdx.x, t = threadIdx.x;
    __shared__ float svel[NJ*3];
    __shared__ float smask[NJ];
    __shared__ float smean[3];
    if (t < NJ) {
        float m = nm[b*NJ + t];
        smask[t] = m;
        #pragma unroll
        for (int d = 0; d < 3; d++)
            svel[t*3+d] = (g_x[(b*NJ+t)*3+d] - g_x0[(b*NJ+t)*3+d]) * m;
    }
    __syncthreads();
    if (t == 0) {
        float s0=0.f,s1=0.f,s2=0.f,n=0.f;
        for (int j = 0; j < NJ; j++) {
            s0 += svel[j*3+0]; s1 += svel[j*3+1]; s2 += svel[j*3+2];
            n  += smask[j];
        }
        smean[0] = s0/n; smean[1] = s1/n; smean[2] = s2/n;
    }
    __syncthreads();
    if (t < NJ) {
        #pragma unroll
        for (int d = 0; d < 3; d++)
            out[(b*NJ+t)*9 + d] = (svel[t*3+d] - smean[d]) * smask[t];
    }
    int w = t >> 5, lane = t & 31;
    for (int i = w; i < NJ; i += 8) {
        float a0=0.f,a1=0.f,a2=0.f,a3=0.f,a4=0.f,a5=0.f;
        const float* hp = g_h + (size_t)(b*NJ + i)*HS;
        for (int k = lane; k < HS; k += 32) {
            float hv = hp[k];
            const float* wr = Wo + k*7;
            a0 += hv*wr[0]; a1 += hv*wr[1]; a2 += hv*wr[2];
            a3 += hv*wr[3]; a4 += hv*wr[4]; a5 += hv*wr[5];
        }
        #pragma unroll
        for (int off = 16; off > 0; off >>= 1) {
            a0 += __shfl_down_sync(0xffffffffu, a0, off);
            a1 += __shfl_down_sync(0xffffffffu, a1, off);
            a2 += __shfl_down_sync(0xffffffffu, a2, off);
            a3 += __shfl_down_sync(0xffffffffu, a3, off);
            a4 += __shfl_down_sync(0xffffffffu, a4, off);
            a5 += __shfl_down_sync(0xffffffffu, a5, off);
        }
        if (lane == 0) {
            float m = smask[i];
            float* o = out + (b*NJ+i)*9;
            o[3] = (a0 + bo[0]) * m;
            o[4] = (a1 + bo[1]) * m;
            o[5] = (a2 + bo[2]) * m;
            o[6] = (a3 + bo[3]) * m;
            o[7] = (a4 + bo[4]) * m;
            o[8] = (a5 + bo[5]) * m;
        }
    }
}

// ---------------- launch ----------------
extern "C" void kernel_launch(void* const* d_in, const int* in_sizes, int n_in,
                              void* d_out, int out_size) {
    (void)in_sizes; (void)n_in; (void)out_size;
    const float* t       = (const float*)d_in[0];
    const float* xh      = (const float*)d_in[1];
    const float* nm      = (const float*)d_in[2];
    const float* em      = (const float*)d_in[3];
    const float* rep     = (const float*)d_in[4];
    const float* W_embed = (const float*)d_in[5];
    const float* b_embed = (const float*)d_in[6];
    const float* W_rep   = (const float*)d_in[7];
    const float* b_rep   = (const float*)d_in[8];
    const float* We1     = (const float*)d_in[9];
    const float* be1     = (const float*)d_in[10];
    const float* We2     = (const float*)d_in[11];
    const float* be2     = (const float*)d_in[12];
    const float* Wn1     = (const float*)d_in[13];
    const float* bn1     = (const float*)d_in[14];
    const float* Wn2     = (const float*)d_in[15];
    const float* bn2     = (const float*)d_in[16];
    const float* Wc1     = (const float*)d_in[17];
    const float* bc1     = (const float*)d_in[18];
    const float* Wc2     = (const float*)d_in[19];
    const float* bc2     = (const float*)d_in[20];
    const float* Wc3     = (const float*)d_in[21];
    const float* W_out   = (const float*)d_in[22];
    const float* b_out   = (const float*)d_in[23];
    float* out = (float*)d_out;

    static bool attr_done = false;
    if (!attr_done) {
        cudaFuncSetAttribute(k_fused, cudaFuncAttributeMaxDynamicSharedMemorySize, FUSED_BYTES);
        cudaFuncSetAttribute(k_pqm,   cudaFuncAttributeMaxDynamicSharedMemorySize, PQM_BYTES);
        cudaFuncSetAttribute(k_nodem, cudaFuncAttributeMaxDynamicSharedMemorySize, NODEM_BYTES);
        attr_done = true;
    }

    k_prepall<<<dim3(8, 8, 60), dim3(32, 8)>>>(We2, Wc2, We1, Wc1, Wn1, Wn2);
    k_init<<<BSZ, 256>>>(xh, nm, t, W_embed, b_embed, rep, W_rep, b_rep);
    k_pqm<<<dim3(GBLK, 2, 1), 256, PQM_BYTES>>>(0, be1, -1, nullptr);

    int k = 0;
    for (int l = 0; l < NLAY; l++) {
        if (l > 0) k_dist<<<BSZ, 256>>>();
        k_fused<<<BSZ*22, 256, FUSED_BYTES>>>(We1 + (size_t)k*514*HS, k,
                                              be2 + k*HS, em, nullptr, nullptr, 0,
                                              (l > 0) ? 1 : 0);
        k_nodem<<<GBLK, 256, NODEM_BYTES>>>(k, bn1 + k*HS, bn2 + k*HS, nm);
        k_pqm<<<dim3(GBLK, 2, 1), 256, PQM_BYTES>>>(k + 1, be1 + (size_t)(k+1)*HS,
                                                    -1, nullptr);
        k++;
        k_fused<<<BSZ*22, 256, FUSED_BYTES>>>(We1 + (size_t)k*514*HS, k,
                                              be2 + k*HS, em, nullptr, nullptr, 0, 0);
        k_nodem<<<GBLK, 256, NODEM_BYTES>>>(k, bn1 + k*HS, bn2 + k*HS, nm);
        if (l < NLAY - 1) {
            k_pqm<<<dim3(GBLK, 2, 2), 256, PQM_BYTES>>>(8 + l, bc1 + (size_t)l*HS,
                                                        k + 1, be1 + (size_t)(k+1)*HS);
        } else {
            k_pqm<<<dim3(GBLK, 2, 1), 256, PQM_BYTES>>>(8 + l, bc1 + (size_t)l*HS,
                                                        -1, nullptr);
        }
        k++;
        k_fused<<<BSZ*22, 256, FUSED_BYTES>>>(Wc1 + (size_t)l*514*HS, 8 + l,
                                              bc2 + l*HS, em, Wc3 + (size_t)l*HS, nm, 1, 0);
    }
    k_out<<<BSZ, 256>>>(nm, W_out, b_out, out);
}

// round 15
// speedup vs baseline: 1.1477x; 1.0041x over previous
#include <cuda_runtime.h>
#include <cuda_bf16.h>
#include <cstdint>

#define BSZ 64
#define NJ  44
#define HS  256
#define REPF 512
#define NLAY 4
#define NROWS (BSZ*NJ)
#define RPB 32
#define GBLK 88

// ---------------- persistent device state ----------------
__device__ float g_h[NROWS*HS];
__device__ float g_agg[NROWS*HS];
__device__ float g_P[NROWS*HS];
__device__ float g_Q[NROWS*HS];
__device__ float g_P2[NROWS*HS];
__device__ float g_Q2[NROWS*HS];
__device__ float g_x[NROWS*3];
__device__ float g_x0[NROWS*3];
__device__ float g_d0[BSZ*NJ*NJ];
__device__ unsigned int g_W2T [12*256*128];     // bf16x2 [m][n][kpair]
__device__ unsigned int g_WpqT[12*2*256*256];   // tf32 [m][half][n][k]
__device__ unsigned int g_Wn1T[8*256*512];      // tf32 [m][n][k]
__device__ unsigned int g_Wn2T[8*256*256];      // tf32 [m][n][k]

__device__ __forceinline__ float silu_f(float x) {
    return x / (1.0f + __expf(-x));
}
__device__ __forceinline__ float silu_t(float x) {
    float t;
    asm("tanh.approx.f32 %0, %1;" : "=f"(t) : "f"(0.5f*x));
    return 0.5f*x*(1.0f + t);
}
__device__ __forceinline__ unsigned int packbf(float lo, float hi) {
    __nv_bfloat162 h2 = __floats2bfloat162_rn(lo, hi);
    return *(unsigned int*)&h2;
}
__device__ __forceinline__ unsigned int f2tf32(float v) {
    unsigned int u;
    asm("cvt.rna.tf32.f32 %0, %1;" : "=r"(u) : "f"(v));
    return u;
}
__device__ __forceinline__ uint32_t sptr(const void* p) {
    uint32_t a;
    asm("{ .reg .u64 t; cvta.to.shared.u64 t, %1; cvt.u32.u64 %0, t; }" : "=r"(a) : "l"(p));
    return a;
}
__device__ __forceinline__ void mma16(float c[4], unsigned a0, unsigned a1,
                                      unsigned a2, unsigned a3,
                                      unsigned b0, unsigned b1) {
    asm volatile("mma.sync.aligned.m16n8k16.row.col.f32.bf16.bf16.f32 "
        "{%0,%1,%2,%3}, {%4,%5,%6,%7}, {%8,%9}, {%0,%1,%2,%3};"
        : "+f"(c[0]), "+f"(c[1]), "+f"(c[2]), "+f"(c[3])
        : "r"(a0), "r"(a1), "r"(a2), "r"(a3), "r"(b0), "r"(b1));
}
__device__ __forceinline__ void mma8(float c[4], unsigned a0, unsigned a1,
                                     unsigned a2, unsigned a3,
                                     unsigned b0, unsigned b1) {
    asm volatile("mma.sync.aligned.m16n8k8.row.col.f32.tf32.tf32.f32 "
        "{%0,%1,%2,%3}, {%4,%5,%6,%7}, {%8,%9}, {%0,%1,%2,%3};"
        : "+f"(c[0]), "+f"(c[1]), "+f"(c[2]), "+f"(c[3])
        : "r"(a0), "r"(a1), "r"(a2), "r"(a3), "r"(b0), "r"(b1));
}
#define LDSM4(r0, r1, r2, r3, addr) \
    asm volatile("ldmatrix.sync.aligned.m8n8.x4.shared.b16 {%0,%1,%2,%3}, [%4];" \
        : "=r"(r0), "=r"(r1), "=r"(r2), "=r"(r3) : "r"(addr))
#define CPA16(dst, src) asm volatile("cp.async.cg.shared.global [%0], [%1], 16;" :: "r"(dst), "l"(src) : "memory")
#define CPA_COMMIT()    asm volatile("cp.async.commit_group;" ::: "memory")
#define CPA_WAIT0()     asm volatile("cp.async.wait_group 0;" ::: "memory")

// ---------------- weight prep (all transposes in one kernel) ----------------
__global__ void k_prepall(const float* __restrict__ We2, const float* __restrict__ Wc2,
                          const float* __restrict__ We1, const float* __restrict__ Wc1,
                          const float* __restrict__ Wn1, const float* __restrict__ Wn2) {
    __shared__ float tile[32][33];
    int z = blockIdx.z;
    int k0 = blockIdx.x*32, n0 = blockIdx.y*32;
    int tx = threadIdx.x, ty = threadIdx.y;
    int tid = ty*32 + tx;
    if (z < 12) {
        int m = z;
        const float* src = (m < 8) ? We2 + (size_t)m*HS*HS : Wc2 + (size_t)(m-8)*HS*HS;
        unsigned int* dst = g_W2T + (size_t)m*256*128;
        #pragma unroll
        for (int q = 0; q < 4; q++)
            tile[ty + 8*q][tx] = src[(size_t)(k0 + ty + 8*q)*HS + n0 + tx];
        __syncthreads();
        for (int o = tid; o < 512; o += 256) {
            int nl = o >> 4, p = o & 15;
            dst[(size_t)(n0 + nl)*128 + (k0 >> 1) + p] = packbf(tile[2*p][nl], tile[2*p+1][nl]);
        }
        return;
    }
    int v = z - 12;
    const float* src; unsigned int* dst; int stride, koff;
    if (v < 24) {
        int m = v >> 1, half = v & 1;
        src = ((m < 8) ? We1 + (size_t)m*514*HS : Wc1 + (size_t)(m-8)*514*HS)
              + (size_t)half*HS*HS;
        dst = g_WpqT + ((size_t)m*2 + half)*65536; stride = 256; koff = 0;
    } else if (v < 40) {
        int u = v - 24, m = u >> 1, kh = u & 1;
        src = Wn1 + (size_t)m*512*HS + (size_t)kh*HS*HS;
        dst = g_Wn1T + (size_t)m*131072; stride = 512; koff = kh*256;
    } else {
        int m = v - 40;
        src = Wn2 + (size_t)m*HS*HS;
        dst = g_Wn2T + (size_t)m*65536; stride = 256; koff = 0;
    }
    #pragma unroll
    for (int q = 0; q < 4; q++)
        tile[ty + 8*q][tx] = src[(size_t)(k0 + ty + 8*q)*HS + n0 + tx];
    __syncthreads();
    for (int o = tid; o < 1024; o += 256) {
        int nl = o >> 5, kk = o & 31;
        dst[(size_t)(n0 + nl)*stride + koff + k0 + kk] = f2tf32(tile[kk][nl]);
    }
}

// ---------------- k_fused smem layout (M=96: 2 edges/block) ----------------
#define F_OD   22912   // [96] squared distances (computed in-kernel)
#define F_OD0  23008
#define F_OMK  23104
#define F_OPS  23200
#define F_OPHI 23968
#define F_SX   24064   // [132] x coords of batch b
#define FUSED_FLOATS 24200
#define FUSED_BYTES (FUSED_FLOATS*4)
#define PQM_BYTES   ((RPB*260 + 2*256*36)*4)
#define NODEM_BYTES ((RPB*516 + 2*256*36 + RPB*260)*4)

// =====================================================================
// Fused edge/coord MLP; block = (b, i-pair): M=96 rows, N=256.
// Distances computed in-kernel from g_x (no k_dist / g_d / g_cdiff).
// =====================================================================
__global__ __launch_bounds__(256, 2) void k_fused(
    const float* __restrict__ W1,
    int mW2,
    const float* __restrict__ b2,
    const float* __restrict__ em,
    const float* __restrict__ W3,
    const float* __restrict__ nm,
    int mode, int pqbuf)
{
    extern __shared__ float S[];
    unsigned int* As = (unsigned int*)S;           // [96][132]
    unsigned int* Bs = As + 96*132;                // 2 x [256][20]
    const unsigned int* W2T = g_W2T + (size_t)mW2*256*128;
    const float* Pp = pqbuf ? g_P2 : g_P;
    const float* Qp = pqbuf ? g_Q2 : g_Q;

    int tid = threadIdx.x, warp = tid >> 5, lane = tid & 31;
    int lane4 = lane >> 2, lanem = lane & 3;
    int b = blockIdx.x / 22, pr = blockIdx.x % 22;
    int i0 = 2*pr;
    uint32_t bsm = sptr(Bs);
    uint32_t asmb = sptr(As);
    int cn = tid >> 2, cq = (tid & 3)*4;

    #pragma unroll
    for (int r = 0; r < 4; r++) {
        int nr = cn + r*64;
        CPA16(bsm + (nr*20 + cq)*4, &W2T[(size_t)nr*128 + cq]);
    }
    CPA_COMMIT();

    if (tid < 132) S[F_SX + tid] = g_x[b*NJ*3 + tid];
    if (tid < 96) {
        int g = tid / 48, j = tid % 48;
        float d0v = 0.f, mv = 0.f;
        if (j < NJ) {
            int e = (b*NJ + i0 + g)*NJ + j;
            d0v = g_d0[e]; mv = em[e];
        }
        S[F_OD0 + tid] = d0v; S[F_OMK + tid] = mv;
    }
    __syncthreads();
    if (tid < 96) {
        int g = tid / 48, j = tid % 48;
        float r = 0.f;
        if (j < NJ) {
            int i = i0 + g;
            float dx = S[F_SX + i*3+0] - S[F_SX + j*3+0];
            float dy = S[F_SX + i*3+1] - S[F_SX + j*3+1];
            float dz = S[F_SX + i*3+2] - S[F_SX + j*3+2];
            r = dx*dx + dy*dy + dz*dz;
        }
        S[F_OD + tid] = r;
    }
    __syncthreads();

    // ---- phase 1 ----
    {
        int cp = tid & 127, jh = tid >> 7;
        float2 Pv0 = *(const float2*)&Pp[(size_t)(b*NJ + i0    )*HS + 2*cp];
        float2 Pv1 = *(const float2*)&Pp[(size_t)(b*NJ + i0 + 1)*HS + 2*cp];
        float2 wdv = *(const float2*)&W1[512*HS + 2*cp];
        float2 wd0v= *(const float2*)&W1[513*HS + 2*cp];
        const float* qbase = Qp + (size_t)b*NJ*HS + 2*cp;
        int j0 = jh * 22;
        #pragma unroll
        for (int batch = 0; batch < 2; batch++) {
            float2 qv[11];
            #pragma unroll
            for (int u = 0; u < 11; u++)
                qv[u] = *(const float2*)&qbase[(size_t)(j0 + batch*11 + u)*HS];
            #pragma unroll
            for (int u = 0; u < 11; u++) {
                int j = j0 + batch*11 + u;
                float dj0 = S[F_OD + j],      d0j0 = S[F_OD0 + j];
                float dj1 = S[F_OD + 48 + j], d0j1 = S[F_OD0 + 48 + j];
                float base0 = qv[u].x, base1 = qv[u].y;
                float v00 = Pv0.x + base0 + wdv.x*dj0 + wd0v.x*d0j0;
                float v01 = Pv0.y + base1 + wdv.y*dj0 + wd0v.y*d0j0;
                float v10 = Pv1.x + base0 + wdv.x*dj1 + wd0v.x*d0j1;
                float v11 = Pv1.y + base1 + wdv.y*dj1 + wd0v.y*d0j1;
                As[j*132 + cp]        = packbf(silu_t(v00), silu_t(v01));
                As[(48 + j)*132 + cp] = packbf(silu_t(v10), silu_t(v11));
            }
        }
        for (int p = tid; p < 4*132; p += 256) {
            As[44*132 + p] = 0u;
            As[92*132 + p] = 0u;
        }
    }
    CPA_WAIT0();
    __syncthreads();

    // ---- phase 2 ----
    float acc[6][4][4];
    #pragma unroll
    for (int mt = 0; mt < 6; mt++)
        #pragma unroll
        for (int nt = 0; nt < 4; nt++)
            #pragma unroll
            for (int q = 0; q < 4; q++) acc[mt][nt][q] = 0.f;

    int l7 = lane & 7, sel = lane >> 3;
    uint32_t abase = asmb + ((((sel & 1)*8 + l7)*132) + (sel >> 1)*4)*4;
    uint32_t baddr[2];
    #pragma unroll
    for (int t = 0; t < 2; t++)
        baddr[t] = bsm + (((warp*32 + t*16 + (sel >> 1)*8 + l7)*20) + (sel & 1)*4)*4;

    for (int kc = 0; kc < 8; kc++) {
        if (kc < 7) {
            uint32_t dsm = bsm + (((kc+1) & 1) ? 256*20*4 : 0);
            #pragma unroll
            for (int r = 0; r < 4; r++) {
                int nr = cn + r*64;
                CPA16(dsm + (nr*20 + cq)*4, &W2T[(size_t)nr*128 + (kc+1)*16 + cq]);
            }
            CPA_COMMIT();
        }
        uint32_t boff = (kc & 1) ? 256*20*4 : 0;
        #pragma unroll
        for (int s = 0; s < 2; s++) {
            uint32_t koff = (uint32_t)(kc*16 + s*8)*4;
            unsigned int bb[8];
            LDSM4(bb[0], bb[1], bb[2], bb[3], baddr[0] + boff + s*8*4);
            LDSM4(bb[4], bb[5], bb[6], bb[7], baddr[1] + boff + s*8*4);
            #pragma unroll
            for (int mt = 0; mt < 6; mt++) {
                unsigned int a0, a1, a2, a3;
                LDSM4(a0, a1, a2, a3, abase + (uint32_t)mt*16*132*4 + koff);
                mma16(acc[mt][0], a0, a1, a2, a3, bb[0], bb[1]);
                mma16(acc[mt][1], a0, a1, a2, a3, bb[2], bb[3]);
                mma16(acc[mt][2], a0, a1, a2, a3, bb[4], bb[5]);
                mma16(acc[mt][3], a0, a1, a2, a3, bb[6], bb[7]);
            }
        }
        if (kc < 7) CPA_WAIT0();
        __syncthreads();
    }

    // ---- epilogue ----
    float msk[12];
    #pragma unroll
    for (int mt = 0; mt < 6; mt++) {
        msk[2*mt]   = S[F_OMK + mt*16 + lane4];
        msk[2*mt+1] = S[F_OMK + mt*16 + lane4 + 8];
    }
    if (mode == 0) {
        #pragma unroll
        for (int g = 0; g < 2; g++) {
            size_t rowbase = (size_t)(b*NJ + i0 + g)*HS;
            #pragma unroll
            for (int nt = 0; nt < 4; nt++) {
                int n = warp*32 + nt*8 + lanem*2;
                float2 bb = *(const float2*)&b2[n];
                float s0 = 0.f, s1 = 0.f;
                #pragma unroll
                for (int mm = 0; mm < 3; mm++) {
                    int mt = g*3 + mm;
                    s0 += silu_t(acc[mt][nt][0] + bb.x)*msk[2*mt]
                        + silu_t(acc[mt][nt][2] + bb.x)*msk[2*mt+1];
                    s1 += silu_t(acc[mt][nt][1] + bb.y)*msk[2*mt]
                        + silu_t(acc[mt][nt][3] + bb.y)*msk[2*mt+1];
                }
                #pragma unroll
                for (int off = 4; off <= 16; off <<= 1) {
                    s0 += __shfl_xor_sync(0xffffffffu, s0, off);
                    s1 += __shfl_xor_sync(0xffffffffu, s1, off);
                }
                if (lane4 == 0)
                    *(float2*)&g_agg[rowbase + n] = make_float2(s0*0.01f, s1*0.01f);
            }
        }
    } else {
        float ph[12];
        #pragma unroll
        for (int q = 0; q < 12; q++) ph[q] = 0.f;
        #pragma unroll
        for (int nt = 0; nt < 4; nt++) {
            int n = warp*32 + nt*8 + lanem*2;
            float2 bb = *(const float2*)&b2[n];
            float2 w3 = *(const float2*)&W3[n];
            #pragma unroll
            for (int mt = 0; mt < 6; mt++) {
                ph[2*mt]   += silu_t(acc[mt][nt][0] + bb.x)*w3.x
                            + silu_t(acc[mt][nt][1] + bb.y)*w3.y;
                ph[2*mt+1] += silu_t(acc[mt][nt][2] + bb.x)*w3.x
                            + silu_t(acc[mt][nt][3] + bb.y)*w3.y;
            }
        }
        #pragma unroll
        for (int q = 0; q < 12; q++) {
            ph[q] += __shfl_xor_sync(0xffffffffu, ph[q], 1);
            ph[q] += __shfl_xor_sync(0xffffffffu, ph[q], 2);
        }
        if (lanem == 0) {
            #pragma unroll
            for (int mt = 0; mt < 6; mt++) {
                S[F_OPS + warp*96 + mt*16 + lane4]     = ph[2*mt];
                S[F_OPS + warp*96 + mt*16 + lane4 + 8] = ph[2*mt+1];
            }
        }
        __syncthreads();
        if (tid < 96) {
            float p = 0.f;
            #pragma unroll
            for (int w = 0; w < 8; w++) p += S[F_OPS + w*96 + tid];
            S[F_OPHI + tid] = p * S[F_OMK + tid];
        }
        __syncthreads();
        // parallel trans reduction: both warps fully active (legal full-mask shfl)
        if (tid < 64) {
            int pair = tid >> 3, t8 = tid & 7;   // pairs 0..7; 6,7 dummy
            int pc = (pair < 6) ? pair : 0;
            int g = pc / 3, d = pc % 3;
            int i = i0 + g;
            float s = 0.f;
            for (int j = t8; j < NJ; j += 8) {
                float r = S[F_OD + g*48 + j];
                float inv = rsqrtf(r + 1e-8f);
                s += (S[F_SX + i*3 + d] - S[F_SX + j*3 + d]) * inv
                     * S[F_OPHI + g*48 + j];
            }
            s += __shfl_down_sync(0xffffffffu, s, 4);
            s += __shfl_down_sync(0xffffffffu, s, 2);
            s += __shfl_down_sync(0xffffffffu, s, 1);
            if (t8 == 0 && pair < 6) {
                float m = nm[b*NJ + i];
                int xi = (b*NJ + i)*3 + d;
                g_x[xi] = (g_x[xi] + s*0.01f) * m;
            }
        }
    }
}

// =====================================================================
// P/Q projection via tf32 mma, M=32/block, grid (88, 2, nsets).
// =====================================================================
__global__ __launch_bounds__(256) void k_pqm(
    int mWA, const float* __restrict__ bA,
    int mWB, const float* __restrict__ bB)
{
    extern __shared__ float S[];
    unsigned int* As = (unsigned int*)S;
    unsigned int* Bs = As + RPB*260;
    int tid = threadIdx.x, warp = tid >> 5, lane = tid & 31;
    int lane4 = lane >> 2, lanem = lane & 3;
    int r0 = blockIdx.x * RPB, half = blockIdx.y, set = blockIdx.z;
    int mW = set ? mWB : mWA;
    const float* b1 = set ? bB : bA;
    const unsigned int* BT = g_WpqT + ((size_t)mW*2 + half)*65536;
    uint32_t bsm = sptr(Bs);

    #pragma unroll
    for (int q = 0; q < 8; q++)
        CPA16(bsm + (tid*36 + q*4)*4, &BT[(size_t)tid*256 + q*4]);
    CPA_COMMIT();

    for (int idx = tid; idx < RPB*256; idx += 256) {
        int row = idx >> 8, k = idx & 255;
        float v = 0.f;
        int gr = r0 + row;
        if (gr < NROWS) v = g_h[(size_t)gr*HS + k];
        As[row*260 + k] = f2tf32(v);
    }
    CPA_WAIT0();
    __syncthreads();

    float acc[2][4][4];
    #pragma unroll
    for (int mt = 0; mt < 2; mt++)
        #pragma unroll
        for (int nt = 0; nt < 4; nt++)
            #pragma unroll
            for (int q = 0; q < 4; q++) acc[mt][nt][q] = 0.f;

    for (int kc = 0; kc < 8; kc++) {
        if (kc < 7) {
            uint32_t dsm = bsm + (((kc+1) & 1) ? 256*36*4 : 0);
            #pragma unroll
            for (int q = 0; q < 8; q++)
                CPA16(dsm + (tid*36 + q*4)*4, &BT[(size_t)tid*256 + (kc+1)*32 + q*4]);
            CPA_COMMIT();
        }
        unsigned int* Bcur = Bs + (kc & 1)*(256*36);
        #pragma unroll
        for (int ks = 0; ks < 4; ks++) {
            int pb = ks*8;
            unsigned int bf0[4], bf1[4];
            #pragma unroll
            for (int nt = 0; nt < 4; nt++) {
                int n = warp*32 + nt*8 + lane4;
                bf0[nt] = Bcur[n*36 + pb + lanem];
                bf1[nt] = Bcur[n*36 + pb + lanem + 4];
            }
            #pragma unroll
            for (int mt = 0; mt < 2; mt++) {
                int r = mt*16 + lane4;
                int kA = kc*32 + pb + lanem;
                unsigned int a0 = As[r*260 + kA];
                unsigned int a1 = As[(r+8)*260 + kA];
                unsigned int a2 = As[r*260 + kA + 4];
                unsigned int a3 = As[(r+8)*260 + kA + 4];
                #pragma unroll
                for (int nt = 0; nt < 4; nt++)
                    mma8(acc[mt][nt], a0, a1, a2, a3, bf0[nt], bf1[nt]);
            }
        }
        if (kc < 7) CPA_WAIT0();
        __syncthreads();
    }

    float* outp = half ? (set ? g_Q2 : g_Q) : (set ? g_P2 : g_P);
    #pragma unroll
    for (int mt = 0; mt < 2; mt++) {
        int r = mt*16 + lane4;
        #pragma unroll
        for (int nt = 0; nt < 4; nt++) {
            int n = warp*32 + nt*8 + lanem*2;
            float2 bb = half ? make_float2(0.f, 0.f) : *(const float2*)&b1[n];
            if (r0 + r < NROWS)
                *(float2*)&outp[(size_t)(r0+r)*HS + n] =
                    make_float2(acc[mt][nt][0] + bb.x, acc[mt][nt][1] + bb.y);
            if (r0 + r + 8 < NROWS)
                *(float2*)&outp[(size_t)(r0+r+8)*HS + n] =
                    make_float2(acc[mt][nt][2] + bb.x, acc[mt][nt][3] + bb.y);
        }
    }
}

// =====================================================================
// Node MLP via tf32 mma, fused 2 layers + residual, M=32, grid 88.
// =====================================================================
__global__ __launch_bounds__(256) void k_nodem(
    int m, const float* __restrict__ b1, const float* __restrict__ b2,
    const float* __restrict__ nm)
{
    extern __shared__ float S[];
    unsigned int* A1 = (unsigned int*)S;
    unsigned int* Bs = A1 + RPB*516;
    unsigned int* A2 = Bs + 2*256*36;
    const unsigned int* B1T = g_Wn1T + (size_t)m*131072;
    const unsigned int* B2T = g_Wn2T + (size_t)m*65536;
    uint32_t bsm = sptr(Bs);

    int tid = threadIdx.x, warp = tid >> 5, lane = tid & 31;
    int lane4 = lane >> 2, lanem = lane & 3;
    int r0 = blockIdx.x * RPB;

    #pragma unroll
    for (int q = 0; q < 8; q++)
        CPA16(bsm + (tid*36 + q*4)*4, &B1T[(size_t)tid*512 + q*4]);
    CPA_COMMIT();

    for (int idx = tid; idx < RPB*512; idx += 256) {
        int row = idx >> 9, k = idx & 511;
        float v = 0.f;
        int gr = r0 + row;
        if (gr < NROWS)
            v = (k < 256) ? g_h[(size_t)gr*HS + k] : g_agg[(size_t)gr*HS + (k-256)];
        A1[row*516 + k] = f2tf32(v);
    }
    CPA_WAIT0();
    __syncthreads();

    float acc[2][4][4];
    #pragma unroll
    for (int mt = 0; mt < 2; mt++)
        #pragma unroll
        for (int nt = 0; nt < 4; nt++)
            #pragma unroll
            for (int q = 0; q < 4; q++) acc[mt][nt][q] = 0.f;

    for (int kc = 0; kc < 16; kc++) {
        if (kc < 15) {
            uint32_t dsm = bsm + (((kc+1) & 1) ? 256*36*4 : 0);
            #pragma unroll
            for (int q = 0; q < 8; q++)
                CPA16(dsm + (tid*36 + q*4)*4, &B1T[(size_t)tid*512 + (kc+1)*32 + q*4]);
            CPA_COMMIT();
        }
        unsigned int* Bcur = Bs + (kc & 1)*(256*36);
        #pragma unroll
        for (int ks = 0; ks < 4; ks++) {
            int pb = ks*8;
            unsigned int bf0[4], bf1[4];
            #pragma unroll
            for (int nt = 0; nt < 4; nt++) {
                int n = warp*32 + nt*8 + lane4;
                bf0[nt] = Bcur[n*36 + pb + lanem];
                bf1[nt] = Bcur[n*36 + pb + lanem + 4];
            }
            #pragma unroll
            for (int mt = 0; mt < 2; mt++) {
                int r = mt*16 + lane4;
                int kA = kc*32 + pb + lanem;
                unsigned int a0 = A1[r*516 + kA];
                unsigned int a1 = A1[(r+8)*516 + kA];
                unsigned int a2 = A1[r*516 + kA + 4];
                unsigned int a3 = A1[(r+8)*516 + kA + 4];
                #pragma unroll
                for (int nt = 0; nt < 4; nt++)
                    mma8(acc[mt][nt], a0, a1, a2, a3, bf0[nt], bf1[nt]);
            }
        }
        if (kc < 15) CPA_WAIT0();
        __syncthreads();
    }

    #pragma unroll
    for (int q = 0; q < 8; q++)
        CPA16(bsm + (tid*36 + q*4)*4, &B2T[(size_t)tid*256 + q*4]);
    CPA_COMMIT();
    #pragma unroll
    for (int mt = 0; mt < 2; mt++) {
        int r = mt*16 + lane4;
        #pragma unroll
        for (int nt = 0; nt < 4; nt++) {
            int n = warp*32 + nt*8 + lanem*2;
            float2 bb = *(const float2*)&b1[n];
            A2[r*260 + n]       = f2tf32(silu_f(acc[mt][nt][0] + bb.x));
            A2[r*260 + n + 1]   = f2tf32(silu_f(acc[mt][nt][1] + bb.y));
            A2[(r+8)*260 + n]   = f2tf32(silu_f(acc[mt][nt][2] + bb.x));
            A2[(r+8)*260 + n+1] = f2tf32(silu_f(acc[mt][nt][3] + bb.y));
        }
    }
    #pragma unroll
    for (int mt = 0; mt < 2; mt++)
        #pragma unroll
        for (int nt = 0; nt < 4; nt++)
            #pragma unroll
            for (int q = 0; q < 4; q++) acc[mt][nt][q] = 0.f;
    CPA_WAIT0();
    __syncthreads();

    for (int kc = 0; kc < 8; kc++) {
        if (kc < 7) {
            uint32_t dsm = bsm + (((kc+1) & 1) ? 256*36*4 : 0);
            #pragma unroll
            for (int q = 0; q < 8; q++)
                CPA16(dsm + (tid*36 + q*4)*4, &B2T[(size_t)tid*256 + (kc+1)*32 + q*4]);
            CPA_COMMIT();
        }
        unsigned int* Bcur = Bs + (kc & 1)*(256*36);
        #pragma unroll
        for (int ks = 0; ks < 4; ks++) {
            int pb = ks*8;
            unsigned int bf0[4], bf1[4];
            #pragma unroll
            for (int nt = 0; nt < 4; nt++) {
                int n = warp*32 + nt*8 + lane4;
                bf0[nt] = Bcur[n*36 + pb + lanem];
                bf1[nt] = Bcur[n*36 + pb + lanem + 4];
            }
            #pragma unroll
            for (int mt = 0; mt < 2; mt++) {
                int r = mt*16 + lane4;
                int kA = kc*32 + pb + lanem;
                unsigned int a0 = A2[r*260 + kA];
                unsigned int a1 = A2[(r+8)*260 + kA];
                unsigned int a2 = A2[r*260 + kA + 4];
                unsigned int a3 = A2[(r+8)*260 + kA + 4];
                #pragma unroll
                for (int nt = 0; nt < 4; nt++)
                    mma8(acc[mt][nt], a0, a1, a2, a3, bf0[nt], bf1[nt]);
            }
        }
        if (kc < 7) CPA_WAIT0();
        __syncthreads();
    }

    #pragma unroll
    for (int mt = 0; mt < 2; mt++) {
        int r = mt*16 + lane4;
        #pragma unroll
        for (int nt = 0; nt < 4; nt++) {
            int n = warp*32 + nt*8 + lanem*2;
            float2 bb = *(const float2*)&b2[n];
            int gr = r0 + r;
            if (gr < NROWS) {
                float mk = nm[gr];
                float2 old = *(float2*)&g_h[(size_t)gr*HS + n];
                *(float2*)&g_h[(size_t)gr*HS + n] =
                    make_float2((old.x + bb.x + acc[mt][nt][0])*mk,
                                (old.y + bb.y + acc[mt][nt][1])*mk);
            }
            int gr2 = gr + 8;
            if (gr2 < NROWS) {
                float mk = nm[gr2];
                float2 old = *(float2*)&g_h[(size_t)gr2*HS + n];
                *(float2*)&g_h[(size_t)gr2*HS + n] =
                    make_float2((old.x + bb.x + acc[mt][nt][2])*mk,
                                (old.y + bb.y + acc[mt][nt][3])*mk);
            }
        }
    }
}

// =====================================================================
// k_init: repproj + embed + x0/x + initial squared distances (d0 only)
// =====================================================================
__global__ __launch_bounds__(256) void k_init(
    const float* __restrict__ xh, const float* __restrict__ nm,
    const float* __restrict__ tt,
    const float* __restrict__ We, const float* __restrict__ be,
    const float* __restrict__ rep, const float* __restrict__ Wr,
    const float* __restrict__ br)
{
    __shared__ float sr[REPF];
    __shared__ float srp[HS];
    __shared__ float sf[NJ*8];
    __shared__ float sx[NJ*3];
    int b = blockIdx.x, c = threadIdx.x;
    sr[c]       = rep[b*REPF + c];
    sr[c + 256] = rep[b*REPF + 256 + c];
    __syncthreads();
    {
        float a0=0.f,a1=0.f,a2=0.f,a3=0.f;
        const float* w = Wr + c;
        #pragma unroll 4
        for (int k = 0; k < REPF; k += 4) {
            a0 += sr[k+0]*w[(k+0)*HS];
            a1 += sr[k+1]*w[(k+1)*HS];
            a2 += sr[k+2]*w[(k+2)*HS];
            a3 += sr[k+3]*w[(k+3)*HS];
        }
        srp[c] = br[c] + be[c] + ((a0+a1)+(a2+a3));
    }
    if (c < NJ) {
        float m = nm[b*NJ + c];
        const float* row = xh + (b*NJ + c)*9;
        #pragma unroll
        for (int d = 0; d < 3; d++) {
            float xv = row[d] * m;
            g_x0[(b*NJ+c)*3 + d] = xv;
            g_x [(b*NJ+c)*3 + d] = xv;
            sx[c*3 + d] = xv;
        }
        #pragma unroll
        for (int k = 0; k < 6; k++) sf[c*8 + k] = row[3+k] * m;
        sf[c*8 + 6] = tt[b];
    }
    __syncthreads();
    {
        float w[7];
        #pragma unroll
        for (int k = 0; k < 7; k++) w[k] = We[k*HS + c];
        for (int i = 0; i < NJ; i++) {
            float a = srp[c];
            #pragma unroll
            for (int k = 0; k < 7; k++) a += sf[i*8 + k] * w[k];
            g_h[(size_t)(b*NJ + i)*HS + c] = a;
        }
    }
    for (int idx = c; idx < NJ*NJ; idx += 256) {
        int i = idx / NJ, j = idx % NJ;
        float dx = sx[i*3+0]-sx[j*3+0];
        float dy = sx[i*3+1]-sx[j*3+1];
        float dz = sx[i*3+2]-sx[j*3+2];
        g_d0[b*NJ*NJ + idx] = dx*dx + dy*dy + dz*dz;
    }
}

// ---------------- output head ----------------
__global__ __launch_bounds__(256) void k_out(const float* __restrict__ nm,
                                             const float* __restrict__ Wo,
                                             const float* __restrict__ bo,
                                             float* __restrict__ out) {
    int b = blockIdx.x, t = threadIdx.x;
    __shared__ float svel[NJ*3];
    __shared__ float smask[NJ];
    __shared__ float smean[3];
    if (t < NJ) {
        float m = nm[b*NJ + t];
        smask[t] = m;
        #pragma unroll
        for (int d = 0; d < 3; d++)
            svel[t*3+d] = (g_x[(b*NJ+t)*3+d] - g_x0[(b*NJ+t)*3+d]) * m;
    }
    __syncthreads();
    if (t == 0) {
        float s0=0.f,s1=0.f,s2=0.f,n=0.f;
        for (int j = 0; j < NJ; j++) {
            s0 += svel[j*3+0]; s1 += svel[j*3+1]; s2 += svel[j*3+2];
            n  += smask[j];
        }
        smean[0] = s0/n; smean[1] = s1/n; smean[2] = s2/n;
    }
    __syncthreads();
    if (t < NJ) {
        #pragma unroll
        for (int d = 0; d < 3; d++)
            out[(b*NJ+t)*9 + d] = (svel[t*3+d] - smean[d]) * smask[t];
    }
    int w = t >> 5, lane = t & 31;
    for (int i = w; i < NJ; i += 8) {
        float a0=0.f,a1=0.f,a2=0.f,a3=0.f,a4=0.f,a5=0.f;
        const float* hp = g_h + (size_t)(b*NJ + i)*HS;
        for (int k = lane; k < HS; k += 32) {
            float hv = hp[k];
            const float* wr = Wo + k*7;
            a0 += hv*wr[0]; a1 += hv*wr[1]; a2 += hv*wr[2];
            a3 += hv*wr[3]; a4 += hv*wr[4]; a5 += hv*wr[5];
        }
        #pragma unroll
        for (int off = 16; off > 0; off >>= 1) {
            a0 += __shfl_down_sync(0xffffffffu, a0, off);
            a1 += __shfl_down_sync(0xffffffffu, a1, off);
            a2 += __shfl_down_sync(0xffffffffu, a2, off);
            a3 += __shfl_down_sync(0xffffffffu, a3, off);
            a4 += __shfl_down_sync(0xffffffffu, a4, off);
            a5 += __shfl_down_sync(0xffffffffu, a5, off);
        }
        if (lane == 0) {
            float m = smask[i];
            float* o = out + (b*NJ+i)*9;
            o[3] = (a0 + bo[0]) * m;
            o[4] = (a1 + bo[1]) * m;
            o[5] = (a2 + bo[2]) * m;
            o[6] = (a3 + bo[3]) * m;
            o[7] = (a4 + bo[4]) * m;
            o[8] = (a5 + bo[5]) * m;
        }
    }
}

// ---------------- launch ----------------
extern "C" void kernel_launch(void* const* d_in, const int* in_sizes, int n_in,
                              void* d_out, int out_size) {
    (void)in_sizes; (void)n_in; (void)out_size;
    const float* t       = (const float*)d_in[0];
    const float* xh      = (const float*)d_in[1];
    const float* nm      = (const float*)d_in[2];
    const float* em      = (const float*)d_in[3];
    const float* rep     = (const float*)d_in[4];
    const float* W_embed = (const float*)d_in[5];
    const float* b_embed = (const float*)d_in[6];
    const float* W_rep   = (const float*)d_in[7];
    const float* b_rep   = (const float*)d_in[8];
    const float* We1     = (const float*)d_in[9];
    const float* be1     = (const float*)d_in[10];
    const float* We2     = (const float*)d_in[11];
    const float* be2     = (const float*)d_in[12];
    const float* Wn1     = (const float*)d_in[13];
    const float* bn1     = (const float*)d_in[14];
    const float* Wn2     = (const float*)d_in[15];
    const float* bn2     = (const float*)d_in[16];
    const float* Wc1     = (const float*)d_in[17];
    const float* bc1     = (const float*)d_in[18];
    const float* Wc2     = (const float*)d_in[19];
    const float* bc2     = (const float*)d_in[20];
    const float* Wc3     = (const float*)d_in[21];
    const float* W_out   = (const float*)d_in[22];
    const float* b_out   = (const float*)d_in[23];
    float* out = (float*)d_out;

    static bool attr_done = false;
    if (!attr_done) {
        cudaFuncSetAttribute(k_fused, cudaFuncAttributeMaxDynamicSharedMemorySize, FUSED_BYTES);
        cudaFuncSetAttribute(k_pqm,   cudaFuncAttributeMaxDynamicSharedMemorySize, PQM_BYTES);
        cudaFuncSetAttribute(k_nodem, cudaFuncAttributeMaxDynamicSharedMemorySize, NODEM_BYTES);
        attr_done = true;
    }

    k_prepall<<<dim3(8, 8, 60), dim3(32, 8)>>>(We2, Wc2, We1, Wc1, Wn1, Wn2);
    k_init<<<BSZ, 256>>>(xh, nm, t, W_embed, b_embed, rep, W_rep, b_rep);
    k_pqm<<<dim3(GBLK, 2, 1), 256, PQM_BYTES>>>(0, be1, -1, nullptr);

    int k = 0;
    for (int l = 0; l < NLAY; l++) {
        k_fused<<<BSZ*22, 256, FUSED_BYTES>>>(We1 + (size_t)k*514*HS, k,
                                              be2 + k*HS, em, nullptr, nullptr, 0,
                                              (l > 0) ? 1 : 0);
        k_nodem<<<GBLK, 256, NODEM_BYTES>>>(k, bn1 + k*HS, bn2 + k*HS, nm);
        k_pqm<<<dim3(GBLK, 2, 1), 256, PQM_BYTES>>>(k + 1, be1 + (size_t)(k+1)*HS,
                                                    -1, nullptr);
        k++;
        k_fused<<<BSZ*22, 256, FUSED_BYTES>>>(We1 + (size_t)k*514*HS, k,
                                              be2 + k*HS, em, nullptr, nullptr, 0, 0);
        k_nodem<<<GBLK, 256, NODEM_BYTES>>>(k, bn1 + k*HS, bn2 + k*HS, nm);
        if (l < NLAY - 1) {
            k_pqm<<<dim3(GBLK, 2, 2), 256, PQM_BYTES>>>(8 + l, bc1 + (size_t)l*HS,
                                                        k + 1, be1 + (size_t)(k+1)*HS);
        } else {
            k_pqm<<<dim3(GBLK, 2, 1), 256, PQM_BYTES>>>(8 + l, bc1 + (size_t)l*HS,
                                                        -1, nullptr);
        }
        k++;
        k_fused<<<BSZ*22, 256, FUSED_BYTES>>>(Wc1 + (size_t)l*514*HS, 8 + l,
                                              bc2 + l*HS, em, Wc3 + (size_t)l*HS, nm, 1, 0);
    }
    k_out<<<BSZ, 256>>>(nm, W_out, b_out, out);
}

// round 16
// speedup vs baseline: 1.1764x; 1.0251x over previous
#include <cuda_runtime.h>
#include <cuda_bf16.h>
#include <cstdint>

#define BSZ 64
#define NJ  44
#define HS  256
#define REPF 512
#define NLAY 4
#define NROWS (BSZ*NJ)
#define RPB 32
#define GBLK 88

// ---------------- persistent device state ----------------
__device__ float g_h[NROWS*HS];
__device__ float g_agg[NROWS*HS];
__device__ float g_P[NROWS*HS];
__device__ float g_Q[NROWS*HS];
__device__ float g_P2[NROWS*HS];
__device__ float g_Q2[NROWS*HS];
__device__ float g_x[NROWS*3];
__device__ float g_x0[NROWS*3];
__device__ float g_d0[BSZ*NJ*NJ];
__device__ unsigned int g_W2T [12*256*128];     // bf16x2 [m][n][kpair]
__device__ unsigned int g_WpqT[12*2*256*256];   // tf32 [m][half][n][k]
__device__ unsigned int g_Wn1T[8*256*512];      // tf32 [m][n][k]
__device__ unsigned int g_Wn2T[8*256*256];      // tf32 [m][n][k]

__device__ __forceinline__ float silu_f(float x) {
    return x / (1.0f + __expf(-x));
}
__device__ __forceinline__ float silu_t(float x) {
    float t;
    asm("tanh.approx.f32 %0, %1;" : "=f"(t) : "f"(0.5f*x));
    return 0.5f*x*(1.0f + t);
}
__device__ __forceinline__ unsigned int packbf(float lo, float hi) {
    __nv_bfloat162 h2 = __floats2bfloat162_rn(lo, hi);
    return *(unsigned int*)&h2;
}
__device__ __forceinline__ unsigned int f2tf32(float v) {
    unsigned int u;
    asm("cvt.rna.tf32.f32 %0, %1;" : "=r"(u) : "f"(v));
    return u;
}
__device__ __forceinline__ uint32_t sptr(const void* p) {
    uint32_t a;
    asm("{ .reg .u64 t; cvta.to.shared.u64 t, %1; cvt.u32.u64 %0, t; }" : "=r"(a) : "l"(p));
    return a;
}
__device__ __forceinline__ void mma16(float c[4], unsigned a0, unsigned a1,
                                      unsigned a2, unsigned a3,
                                      unsigned b0, unsigned b1) {
    asm volatile("mma.sync.aligned.m16n8k16.row.col.f32.bf16.bf16.f32 "
        "{%0,%1,%2,%3}, {%4,%5,%6,%7}, {%8,%9}, {%0,%1,%2,%3};"
        : "+f"(c[0]), "+f"(c[1]), "+f"(c[2]), "+f"(c[3])
        : "r"(a0), "r"(a1), "r"(a2), "r"(a3), "r"(b0), "r"(b1));
}
__device__ __forceinline__ void mma8(float c[4], unsigned a0, unsigned a1,
                                     unsigned a2, unsigned a3,
                                     unsigned b0, unsigned b1) {
    asm volatile("mma.sync.aligned.m16n8k8.row.col.f32.tf32.tf32.f32 "
        "{%0,%1,%2,%3}, {%4,%5,%6,%7}, {%8,%9}, {%0,%1,%2,%3};"
        : "+f"(c[0]), "+f"(c[1]), "+f"(c[2]), "+f"(c[3])
        : "r"(a0), "r"(a1), "r"(a2), "r"(a3), "r"(b0), "r"(b1));
}
#define LDSM4(r0, r1, r2, r3, addr) \
    asm volatile("ldmatrix.sync.aligned.m8n8.x4.shared.b16 {%0,%1,%2,%3}, [%4];" \
        : "=r"(r0), "=r"(r1), "=r"(r2), "=r"(r3) : "r"(addr))
#define CPA16(dst, src) asm volatile("cp.async.cg.shared.global [%0], [%1], 16;" :: "r"(dst), "l"(src) : "memory")
#define CPA_COMMIT()    asm volatile("cp.async.commit_group;" ::: "memory")
#define CPA_WAIT0()     asm volatile("cp.async.wait_group 0;" ::: "memory")

// ---------------- weight prep + init (merged, z-dispatch) ----------------
__global__ void k_prepall(const float* __restrict__ We2, const float* __restrict__ Wc2,
                          const float* __restrict__ We1, const float* __restrict__ Wc1,
                          const float* __restrict__ Wn1, const float* __restrict__ Wn2,
                          const float* __restrict__ xh, const float* __restrict__ nm,
                          const float* __restrict__ tt,
                          const float* __restrict__ We, const float* __restrict__ be,
                          const float* __restrict__ rep, const float* __restrict__ Wr,
                          const float* __restrict__ br) {
    __shared__ float tile[32][33];
    __shared__ float sr[REPF];
    __shared__ float srp[HS];
    __shared__ float sf[NJ*8];
    __shared__ float sx[NJ*3];
    int z = blockIdx.z;
    int tx = threadIdx.x, ty = threadIdx.y;
    int tid = ty*32 + tx;
    if (z == 60) {
        // ---- init branch: one of 64 batches per (x,y) block ----
        int b = blockIdx.y*8 + blockIdx.x;
        int c = tid;
        sr[c]       = rep[b*REPF + c];
        sr[c + 256] = rep[b*REPF + 256 + c];
        __syncthreads();
        {
            float a0=0.f,a1=0.f,a2=0.f,a3=0.f;
            const float* w = Wr + c;
            #pragma unroll 4
            for (int k = 0; k < REPF; k += 4) {
                a0 += sr[k+0]*w[(k+0)*HS];
                a1 += sr[k+1]*w[(k+1)*HS];
                a2 += sr[k+2]*w[(k+2)*HS];
                a3 += sr[k+3]*w[(k+3)*HS];
            }
            srp[c] = br[c] + be[c] + ((a0+a1)+(a2+a3));
        }
        if (c < NJ) {
            float m = nm[b*NJ + c];
            const float* row = xh + (b*NJ + c)*9;
            #pragma unroll
            for (int d = 0; d < 3; d++) {
                float xv = row[d] * m;
                g_x0[(b*NJ+c)*3 + d] = xv;
                g_x [(b*NJ+c)*3 + d] = xv;
                sx[c*3 + d] = xv;
            }
            #pragma unroll
            for (int k = 0; k < 6; k++) sf[c*8 + k] = row[3+k] * m;
            sf[c*8 + 6] = tt[b];
        }
        __syncthreads();
        {
            float w[7];
            #pragma unroll
            for (int k = 0; k < 7; k++) w[k] = We[k*HS + c];
            for (int i = 0; i < NJ; i++) {
                float a = srp[c];
                #pragma unroll
                for (int k = 0; k < 7; k++) a += sf[i*8 + k] * w[k];
                g_h[(size_t)(b*NJ + i)*HS + c] = a;
            }
        }
        for (int idx = c; idx < NJ*NJ; idx += 256) {
            int i = idx / NJ, j = idx % NJ;
            float dx = sx[i*3+0]-sx[j*3+0];
            float dy = sx[i*3+1]-sx[j*3+1];
            float dz = sx[i*3+2]-sx[j*3+2];
            g_d0[b*NJ*NJ + idx] = dx*dx + dy*dy + dz*dz;
        }
        return;
    }
    int k0 = blockIdx.x*32, n0 = blockIdx.y*32;
    if (z < 12) {
        int m = z;
        const float* src = (m < 8) ? We2 + (size_t)m*HS*HS : Wc2 + (size_t)(m-8)*HS*HS;
        unsigned int* dst = g_W2T + (size_t)m*256*128;
        #pragma unroll
        for (int q = 0; q < 4; q++)
            tile[ty + 8*q][tx] = src[(size_t)(k0 + ty + 8*q)*HS + n0 + tx];
        __syncthreads();
        for (int o = tid; o < 512; o += 256) {
            int nl = o >> 4, p = o & 15;
            dst[(size_t)(n0 + nl)*128 + (k0 >> 1) + p] = packbf(tile[2*p][nl], tile[2*p+1][nl]);
        }
        return;
    }
    int v = z - 12;
    const float* src; unsigned int* dst; int stride, koff;
    if (v < 24) {
        int m = v >> 1, half = v & 1;
        src = ((m < 8) ? We1 + (size_t)m*514*HS : Wc1 + (size_t)(m-8)*514*HS)
              + (size_t)half*HS*HS;
        dst = g_WpqT + ((size_t)m*2 + half)*65536; stride = 256; koff = 0;
    } else if (v < 40) {
        int u = v - 24, m = u >> 1, kh = u & 1;
        src = Wn1 + (size_t)m*512*HS + (size_t)kh*HS*HS;
        dst = g_Wn1T + (size_t)m*131072; stride = 512; koff = kh*256;
    } else {
        int m = v - 40;
        src = Wn2 + (size_t)m*HS*HS;
        dst = g_Wn2T + (size_t)m*65536; stride = 256; koff = 0;
    }
    #pragma unroll
    for (int q = 0; q < 4; q++)
        tile[ty + 8*q][tx] = src[(size_t)(k0 + ty + 8*q)*HS + n0 + tx];
    __syncthreads();
    for (int o = tid; o < 1024; o += 256) {
        int nl = o >> 5, kk = o & 31;
        dst[(size_t)(n0 + nl)*stride + koff + k0 + kk] = f2tf32(tile[kk][nl]);
    }
}

// ---------------- k_fused smem layout (M=96: 2 edges/block) ----------------
#define F_OD   22912
#define F_OD0  23008
#define F_OMK  23104
#define F_OPS  23200
#define F_OPHI 23968
#define F_SX   24064
#define FUSED_FLOATS 24200
#define FUSED_BYTES (FUSED_FLOATS*4)
#define PQM_BYTES   ((RPB*260 + 2*256*36)*4)
#define NODEM_BYTES ((RPB*516 + 2*256*36 + RPB*260)*4)

// =====================================================================
// Fused edge/coord MLP; block = (b, i-pair): M=96 rows, N=256.
// =====================================================================
__global__ __launch_bounds__(256, 2) void k_fused(
    const float* __restrict__ W1,
    int mW2,
    const float* __restrict__ b2,
    const float* __restrict__ em,
    const float* __restrict__ W3,
    const float* __restrict__ nm,
    int mode, int pqbuf)
{
    extern __shared__ float S[];
    unsigned int* As = (unsigned int*)S;           // [96][132]
    unsigned int* Bs = As + 96*132;                // 2 x [256][20]
    const unsigned int* W2T = g_W2T + (size_t)mW2*256*128;
    const float* Pp = pqbuf ? g_P2 : g_P;
    const float* Qp = pqbuf ? g_Q2 : g_Q;

    int tid = threadIdx.x, warp = tid >> 5, lane = tid & 31;
    int lane4 = lane >> 2, lanem = lane & 3;
    int b = blockIdx.x / 22, pr = blockIdx.x % 22;
    int i0 = 2*pr;
    uint32_t bsm = sptr(Bs);
    uint32_t asmb = sptr(As);
    int cn = tid >> 2, cq = (tid & 3)*4;

    #pragma unroll
    for (int r = 0; r < 4; r++) {
        int nr = cn + r*64;
        CPA16(bsm + (nr*20 + cq)*4, &W2T[(size_t)nr*128 + cq]);
    }
    CPA_COMMIT();

    if (tid < 132) S[F_SX + tid] = g_x[b*NJ*3 + tid];
    if (tid < 96) {
        int g = tid / 48, j = tid % 48;
        float d0v = 0.f, mv = 0.f;
        if (j < NJ) {
            int e = (b*NJ + i0 + g)*NJ + j;
            d0v = g_d0[e]; mv = em[e];
        }
        S[F_OD0 + tid] = d0v; S[F_OMK + tid] = mv;
    }
    __syncthreads();
    if (tid < 96) {
        int g = tid / 48, j = tid % 48;
        float r = 0.f;
        if (j < NJ) {
            int i = i0 + g;
            float dx = S[F_SX + i*3+0] - S[F_SX + j*3+0];
            float dy = S[F_SX + i*3+1] - S[F_SX + j*3+1];
            float dz = S[F_SX + i*3+2] - S[F_SX + j*3+2];
            r = dx*dx + dy*dy + dz*dz;
        }
        S[F_OD + tid] = r;
    }
    __syncthreads();

    // ---- phase 1 ----
    {
        int cp = tid & 127, jh = tid >> 7;
        float2 Pv0 = *(const float2*)&Pp[(size_t)(b*NJ + i0    )*HS + 2*cp];
        float2 Pv1 = *(const float2*)&Pp[(size_t)(b*NJ + i0 + 1)*HS + 2*cp];
        float2 wdv = *(const float2*)&W1[512*HS + 2*cp];
        float2 wd0v= *(const float2*)&W1[513*HS + 2*cp];
        const float* qbase = Qp + (size_t)b*NJ*HS + 2*cp;
        int j0 = jh * 22;
        #pragma unroll
        for (int batch = 0; batch < 2; batch++) {
            float2 qv[11];
            #pragma unroll
            for (int u = 0; u < 11; u++)
                qv[u] = *(const float2*)&qbase[(size_t)(j0 + batch*11 + u)*HS];
            #pragma unroll
            for (int u = 0; u < 11; u++) {
                int j = j0 + batch*11 + u;
                float dj0 = S[F_OD + j],      d0j0 = S[F_OD0 + j];
                float dj1 = S[F_OD + 48 + j], d0j1 = S[F_OD0 + 48 + j];
                float base0 = qv[u].x, base1 = qv[u].y;
                float v00 = Pv0.x + base0 + wdv.x*dj0 + wd0v.x*d0j0;
                float v01 = Pv0.y + base1 + wdv.y*dj0 + wd0v.y*d0j0;
                float v10 = Pv1.x + base0 + wdv.x*dj1 + wd0v.x*d0j1;
                float v11 = Pv1.y + base1 + wdv.y*dj1 + wd0v.y*d0j1;
                As[j*132 + cp]        = packbf(silu_t(v00), silu_t(v01));
                As[(48 + j)*132 + cp] = packbf(silu_t(v10), silu_t(v11));
            }
        }
        for (int p = tid; p < 4*132; p += 256) {
            As[44*132 + p] = 0u;
            As[92*132 + p] = 0u;
        }
    }
    CPA_WAIT0();
    __syncthreads();

    // ---- phase 2 ----
    float acc[6][4][4];
    #pragma unroll
    for (int mt = 0; mt < 6; mt++)
        #pragma unroll
        for (int nt = 0; nt < 4; nt++)
            #pragma unroll
            for (int q = 0; q < 4; q++) acc[mt][nt][q] = 0.f;

    int l7 = lane & 7, sel = lane >> 3;
    uint32_t abase = asmb + ((((sel & 1)*8 + l7)*132) + (sel >> 1)*4)*4;
    uint32_t baddr[2];
    #pragma unroll
    for (int t = 0; t < 2; t++)
        baddr[t] = bsm + (((warp*32 + t*16 + (sel >> 1)*8 + l7)*20) + (sel & 1)*4)*4;

    for (int kc = 0; kc < 8; kc++) {
        if (kc < 7) {
            uint32_t dsm = bsm + (((kc+1) & 1) ? 256*20*4 : 0);
            #pragma unroll
            for (int r = 0; r < 4; r++) {
                int nr = cn + r*64;
                CPA16(dsm + (nr*20 + cq)*4, &W2T[(size_t)nr*128 + (kc+1)*16 + cq]);
            }
            CPA_COMMIT();
        }
        uint32_t boff = (kc & 1) ? 256*20*4 : 0;
        #pragma unroll
        for (int s = 0; s < 2; s++) {
            uint32_t koff = (uint32_t)(kc*16 + s*8)*4;
            unsigned int bb[8];
            LDSM4(bb[0], bb[1], bb[2], bb[3], baddr[0] + boff + s*8*4);
            LDSM4(bb[4], bb[5], bb[6], bb[7], baddr[1] + boff + s*8*4);
            #pragma unroll
            for (int mt = 0; mt < 6; mt++) {
                unsigned int a0, a1, a2, a3;
                LDSM4(a0, a1, a2, a3, abase + (uint32_t)mt*16*132*4 + koff);
                mma16(acc[mt][0], a0, a1, a2, a3, bb[0], bb[1]);
                mma16(acc[mt][1], a0, a1, a2, a3, bb[2], bb[3]);
                mma16(acc[mt][2], a0, a1, a2, a3, bb[4], bb[5]);
                mma16(acc[mt][3], a0, a1, a2, a3, bb[6], bb[7]);
            }
        }
        if (kc < 7) CPA_WAIT0();
        __syncthreads();
    }

    // ---- epilogue ----
    float msk[12];
    #pragma unroll
    for (int mt = 0; mt < 6; mt++) {
        msk[2*mt]   = S[F_OMK + mt*16 + lane4];
        msk[2*mt+1] = S[F_OMK + mt*16 + lane4 + 8];
    }
    if (mode == 0) {
        #pragma unroll
        for (int g = 0; g < 2; g++) {
            size_t rowbase = (size_t)(b*NJ + i0 + g)*HS;
            #pragma unroll
            for (int nt = 0; nt < 4; nt++) {
                int n = warp*32 + nt*8 + lanem*2;
                float2 bb = *(const float2*)&b2[n];
                float s0 = 0.f, s1 = 0.f;
                #pragma unroll
                for (int mm = 0; mm < 3; mm++) {
                    int mt = g*3 + mm;
                    s0 += silu_t(acc[mt][nt][0] + bb.x)*msk[2*mt]
                        + silu_t(acc[mt][nt][2] + bb.x)*msk[2*mt+1];
                    s1 += silu_t(acc[mt][nt][1] + bb.y)*msk[2*mt]
                        + silu_t(acc[mt][nt][3] + bb.y)*msk[2*mt+1];
                }
                #pragma unroll
                for (int off = 4; off <= 16; off <<= 1) {
                    s0 += __shfl_xor_sync(0xffffffffu, s0, off);
                    s1 += __shfl_xor_sync(0xffffffffu, s1, off);
                }
                if (lane4 == 0)
                    *(float2*)&g_agg[rowbase + n] = make_float2(s0*0.01f, s1*0.01f);
            }
        }
    } else {
        float ph[12];
        #pragma unroll
        for (int q = 0; q < 12; q++) ph[q] = 0.f;
        #pragma unroll
        for (int nt = 0; nt < 4; nt++) {
            int n = warp*32 + nt*8 + lanem*2;
            float2 bb = *(const float2*)&b2[n];
            float2 w3 = *(const float2*)&W3[n];
            #pragma unroll
            for (int mt = 0; mt < 6; mt++) {
                ph[2*mt]   += silu_t(acc[mt][nt][0] + bb.x)*w3.x
                            + silu_t(acc[mt][nt][1] + bb.y)*w3.y;
                ph[2*mt+1] += silu_t(acc[mt][nt][2] + bb.x)*w3.x
                            + silu_t(acc[mt][nt][3] + bb.y)*w3.y;
            }
        }
        #pragma unroll
        for (int q = 0; q < 12; q++) {
            ph[q] += __shfl_xor_sync(0xffffffffu, ph[q], 1);
            ph[q] += __shfl_xor_sync(0xffffffffu, ph[q], 2);
        }
        if (lanem == 0) {
            #pragma unroll
            for (int mt = 0; mt < 6; mt++) {
                S[F_OPS + warp*96 + mt*16 + lane4]     = ph[2*mt];
                S[F_OPS + warp*96 + mt*16 + lane4 + 8] = ph[2*mt+1];
            }
        }
        __syncthreads();
        if (tid < 96) {
            float p = 0.f;
            #pragma unroll
            for (int w = 0; w < 8; w++) p += S[F_OPS + w*96 + tid];
            S[F_OPHI + tid] = p * S[F_OMK + tid];
        }
        __syncthreads();
        if (tid < 64) {
            int pair = tid >> 3, t8 = tid & 7;
            int pc = (pair < 6) ? pair : 0;
            int g = pc / 3, d = pc % 3;
            int i = i0 + g;
            float s = 0.f;
            for (int j = t8; j < NJ; j += 8) {
                float r = S[F_OD + g*48 + j];
                float inv = rsqrtf(r + 1e-8f);
                s += (S[F_SX + i*3 + d] - S[F_SX + j*3 + d]) * inv
                     * S[F_OPHI + g*48 + j];
            }
            s += __shfl_down_sync(0xffffffffu, s, 4);
            s += __shfl_down_sync(0xffffffffu, s, 2);
            s += __shfl_down_sync(0xffffffffu, s, 1);
            if (t8 == 0 && pair < 6) {
                float m = nm[b*NJ + i];
                int xi = (b*NJ + i)*3 + d;
                g_x[xi] = (g_x[xi] + s*0.01f) * m;
            }
        }
    }
}

// =====================================================================
// P/Q projection via tf32 mma, M=32/block, grid (88, 2, nsets).
// A tile cp.async'd raw (fp32 bits as tf32 operand, RZ truncation).
// =====================================================================
__global__ __launch_bounds__(256) void k_pqm(
    int mWA, const float* __restrict__ bA,
    int mWB, const float* __restrict__ bB)
{
    extern __shared__ float S[];
    unsigned int* As = (unsigned int*)S;     // [32][260]
    unsigned int* Bs = As + RPB*260;
    int tid = threadIdx.x, warp = tid >> 5, lane = tid & 31;
    int lane4 = lane >> 2, lanem = lane & 3;
    int r0 = blockIdx.x * RPB, half = blockIdx.y, set = blockIdx.z;
    int mW = set ? mWB : mWA;
    const float* b1 = set ? bB : bA;
    const unsigned int* BT = g_WpqT + ((size_t)mW*2 + half)*65536;
    uint32_t bsm = sptr(Bs);
    uint32_t asmu = sptr(As);

    #pragma unroll
    for (int q = 0; q < 8; q++)
        CPA16(bsm + (tid*36 + q*4)*4, &BT[(size_t)tid*256 + q*4]);
    // A tile: 32 rows x 256 fp32 via cp.async (8 threads/row)
    {
        int row = tid >> 3, t8 = tid & 7;
        const float* srcrow = g_h + (size_t)(r0 + row)*HS + t8*32;
        uint32_t dstrow = asmu + (row*260 + t8*32)*4;
        #pragma unroll
        for (int q = 0; q < 8; q++)
            CPA16(dstrow + q*16, srcrow + q*4);
    }
    CPA_COMMIT();
    CPA_WAIT0();
    __syncthreads();

    float acc[2][4][4];
    #pragma unroll
    for (int mt = 0; mt < 2; mt++)
        #pragma unroll
        for (int nt = 0; nt < 4; nt++)
            #pragma unroll
            for (int q = 0; q < 4; q++) acc[mt][nt][q] = 0.f;

    for (int kc = 0; kc < 8; kc++) {
        if (kc < 7) {
            uint32_t dsm = bsm + (((kc+1) & 1) ? 256*36*4 : 0);
            #pragma unroll
            for (int q = 0; q < 8; q++)
                CPA16(dsm + (tid*36 + q*4)*4, &BT[(size_t)tid*256 + (kc+1)*32 + q*4]);
            CPA_COMMIT();
        }
        unsigned int* Bcur = Bs + (kc & 1)*(256*36);
        #pragma unroll
        for (int ks = 0; ks < 4; ks++) {
            int pb = ks*8;
            unsigned int bf0[4], bf1[4];
            #pragma unroll
            for (int nt = 0; nt < 4; nt++) {
                int n = warp*32 + nt*8 + lane4;
                bf0[nt] = Bcur[n*36 + pb + lanem];
                bf1[nt] = Bcur[n*36 + pb + lanem + 4];
            }
            #pragma unroll
            for (int mt = 0; mt < 2; mt++) {
                int r = mt*16 + lane4;
                int kA = kc*32 + pb + lanem;
                unsigned int a0 = As[r*260 + kA];
                unsigned int a1 = As[(r+8)*260 + kA];
                unsigned int a2 = As[r*260 + kA + 4];
                unsigned int a3 = As[(r+8)*260 + kA + 4];
                #pragma unroll
                for (int nt = 0; nt < 4; nt++)
                    mma8(acc[mt][nt], a0, a1, a2, a3, bf0[nt], bf1[nt]);
            }
        }
        if (kc < 7) CPA_WAIT0();
        __syncthreads();
    }

    float* outp = half ? (set ? g_Q2 : g_Q) : (set ? g_P2 : g_P);
    #pragma unroll
    for (int mt = 0; mt < 2; mt++) {
        int r = mt*16 + lane4;
        #pragma unroll
        for (int nt = 0; nt < 4; nt++) {
            int n = warp*32 + nt*8 + lanem*2;
            float2 bb = half ? make_float2(0.f, 0.f) : *(const float2*)&b1[n];
            *(float2*)&outp[(size_t)(r0+r)*HS + n] =
                make_float2(acc[mt][nt][0] + bb.x, acc[mt][nt][1] + bb.y);
            *(float2*)&outp[(size_t)(r0+r+8)*HS + n] =
                make_float2(acc[mt][nt][2] + bb.x, acc[mt][nt][3] + bb.y);
        }
    }
}

// =====================================================================
// Node MLP via tf32 mma, fused 2 layers + residual, M=32, grid 88.
// A1 tile cp.async'd raw (h ‖ agg), RZ-truncated tf32 operands.
// =====================================================================
__global__ __launch_bounds__(256) void k_nodem(
    int m, const float* __restrict__ b1, const float* __restrict__ b2,
    const float* __restrict__ nm)
{
    extern __shared__ float S[];
    unsigned int* A1 = (unsigned int*)S;     // [32][516]
    unsigned int* Bs = A1 + RPB*516;
    unsigned int* A2 = Bs + 2*256*36;
    const unsigned int* B1T = g_Wn1T + (size_t)m*131072;
    const unsigned int* B2T = g_Wn2T + (size_t)m*65536;
    uint32_t bsm = sptr(Bs);
    uint32_t a1u = sptr(A1);

    int tid = threadIdx.x, warp = tid >> 5, lane = tid & 31;
    int lane4 = lane >> 2, lanem = lane & 3;
    int r0 = blockIdx.x * RPB;

    #pragma unroll
    for (int q = 0; q < 8; q++)
        CPA16(bsm + (tid*36 + q*4)*4, &B1T[(size_t)tid*512 + q*4]);
    // A1 tile: 32 rows x (256 h + 256 agg) via cp.async
    {
        int row = tid >> 3, t8 = tid & 7;
        const float* hrow = g_h   + (size_t)(r0 + row)*HS;
        const float* arow = g_agg + (size_t)(r0 + row)*HS;
        uint32_t dstrow = a1u + (row*516)*4;
        #pragma unroll
        for (int q = 0; q < 8; q++) {
            int foff = q*32 + t8*4;
            CPA16(dstrow + foff*4, hrow + foff);
        }
        #pragma unroll
        for (int q = 8; q < 16; q++) {
            int foff = q*32 + t8*4;
            CPA16(dstrow + foff*4, arow + (foff - 256));
        }
    }
    CPA_COMMIT();
    CPA_WAIT0();
    __syncthreads();

    float acc[2][4][4];
    #pragma unroll
    for (int mt = 0; mt < 2; mt++)
        #pragma unroll
        for (int nt = 0; nt < 4; nt++)
            #pragma unroll
            for (int q = 0; q < 4; q++) acc[mt][nt][q] = 0.f;

    for (int kc = 0; kc < 16; kc++) {
        if (kc < 15) {
            uint32_t dsm = bsm + (((kc+1) & 1) ? 256*36*4 : 0);
            #pragma unroll
            for (int q = 0; q < 8; q++)
                CPA16(dsm + (tid*36 + q*4)*4, &B1T[(size_t)tid*512 + (kc+1)*32 + q*4]);
            CPA_COMMIT();
        }
        unsigned int* Bcur = Bs + (kc & 1)*(256*36);
        #pragma unroll
        for (int ks = 0; ks < 4; ks++) {
            int pb = ks*8;
            unsigned int bf0[4], bf1[4];
            #pragma unroll
            for (int nt = 0; nt < 4; nt++) {
                int n = warp*32 + nt*8 + lane4;
                bf0[nt] = Bcur[n*36 + pb + lanem];
                bf1[nt] = Bcur[n*36 + pb + lanem + 4];
            }
            #pragma unroll
            for (int mt = 0; mt < 2; mt++) {
                int r = mt*16 + lane4;
                int kA = kc*32 + pb + lanem;
                unsigned int a0 = A1[r*516 + kA];
                unsigned int a1 = A1[(r+8)*516 + kA];
                unsigned int a2 = A1[r*516 + kA + 4];
                unsigned int a3 = A1[(r+8)*516 + kA + 4];
                #pragma unroll
                for (int nt = 0; nt < 4; nt++)
                    mma8(acc[mt][nt], a0, a1, a2, a3, bf0[nt], bf1[nt]);
            }
        }
        if (kc < 15) CPA_WAIT0();
        __syncthreads();
    }

    #pragma unroll
    for (int q = 0; q < 8; q++)
        CPA16(bsm + (tid*36 + q*4)*4, &B2T[(size_t)tid*256 + q*4]);
    CPA_COMMIT();
    #pragma unroll
    for (int mt = 0; mt < 2; mt++) {
        int r = mt*16 + lane4;
        #pragma unroll
        for (int nt = 0; nt < 4; nt++) {
            int n = warp*32 + nt*8 + lanem*2;
            float2 bb = *(const float2*)&b1[n];
            A2[r*260 + n]       = f2tf32(silu_f(acc[mt][nt][0] + bb.x));
            A2[r*260 + n + 1]   = f2tf32(silu_f(acc[mt][nt][1] + bb.y));
            A2[(r+8)*260 + n]   = f2tf32(silu_f(acc[mt][nt][2] + bb.x));
            A2[(r+8)*260 + n+1] = f2tf32(silu_f(acc[mt][nt][3] + bb.y));
        }
    }
    #pragma unroll
    for (int mt = 0; mt < 2; mt++)
        #pragma unroll
        for (int nt = 0; nt < 4; nt++)
            #pragma unroll
            for (int q = 0; q < 4; q++) acc[mt][nt][q] = 0.f;
    CPA_WAIT0();
    __syncthreads();

    for (int kc = 0; kc < 8; kc++) {
        if (kc < 7) {
            uint32_t dsm = bsm + (((kc+1) & 1) ? 256*36*4 : 0);
            #pragma unroll
            for (int q = 0; q < 8; q++)
                CPA16(dsm + (tid*36 + q*4)*4, &B2T[(size_t)tid*256 + (kc+1)*32 + q*4]);
            CPA_COMMIT();
        }
        unsigned int* Bcur = Bs + (kc & 1)*(256*36);
        #pragma unroll
        for (int ks = 0; ks < 4; ks++) {
            int pb = ks*8;
            unsigned int bf0[4], bf1[4];
            #pragma unroll
            for (int nt = 0; nt < 4; nt++) {
                int n = warp*32 + nt*8 + lane4;
                bf0[nt] = Bcur[n*36 + pb + lanem];
                bf1[nt] = Bcur[n*36 + pb + lanem + 4];
            }
            #pragma unroll
            for (int mt = 0; mt < 2; mt++) {
                int r = mt*16 + lane4;
                int kA = kc*32 + pb + lanem;
                unsigned int a0 = A2[r*260 + kA];
                unsigned int a1 = A2[(r+8)*260 + kA];
                unsigned int a2 = A2[r*260 + kA + 4];
                unsigned int a3 = A2[(r+8)*260 + kA + 4];
                #pragma unroll
                for (int nt = 0; nt < 4; nt++)
                    mma8(acc[mt][nt], a0, a1, a2, a3, bf0[nt], bf1[nt]);
            }
        }
        if (kc < 7) CPA_WAIT0();
        __syncthreads();
    }

    #pragma unroll
    for (int mt = 0; mt < 2; mt++) {
        int r = mt*16 + lane4;
        #pragma unroll
        for (int nt = 0; nt < 4; nt++) {
            int n = warp*32 + nt*8 + lanem*2;
            float2 bb = *(const float2*)&b2[n];
            int gr = r0 + r;
            {
                float mk = nm[gr];
                float2 old = *(float2*)&g_h[(size_t)gr*HS + n];
                *(float2*)&g_h[(size_t)gr*HS + n] =
                    make_float2((old.x + bb.x + acc[mt][nt][0])*mk,
                                (old.y + bb.y + acc[mt][nt][1])*mk);
            }
            int gr2 = gr + 8;
            {
                float mk = nm[gr2];
                float2 old = *(float2*)&g_h[(size_t)gr2*HS + n];
                *(float2*)&g_h[(size_t)gr2*HS + n] =
                    make_float2((old.x + bb.x + acc[mt][nt][2])*mk,
                                (old.y + bb.y + acc[mt][nt][3])*mk);
            }
        }
    }
}

// ---------------- output head ----------------
__global__ __launch_bounds__(256) void k_out(const float* __restrict__ nm,
                                             const float* __restrict__ Wo,
                                             const float* __restrict__ bo,
                                             float* __restrict__ out) {
    int b = blockIdx.x, t = threadIdx.x;
    __shared__ float svel[NJ*3];
    __shared__ float smask[NJ];
    __shared__ float smean[3];
    if (t < NJ) {
        float m = nm[b*NJ + t];
        smask[t] = m;
        #pragma unroll
        for (int d = 0; d < 3; d++)
            svel[t*3+d] = (g_x[(b*NJ+t)*3+d] - g_x0[(b*NJ+t)*3+d]) * m;
    }
    __syncthreads();
    if (t == 0) {
        float s0=0.f,s1=0.f,s2=0.f,n=0.f;
        for (int j = 0; j < NJ; j++) {
            s0 += svel[j*3+0]; s1 += svel[j*3+1]; s2 += svel[j*3+2];
            n  += smask[j];
        }
        smean[0] = s0/n; smean[1] = s1/n; smean[2] = s2/n;
    }
    __syncthreads();
    if (t < NJ) {
        #pragma unroll
        for (int d = 0; d < 3; d++)
            out[(b*NJ+t)*9 + d] = (svel[t*3+d] - smean[d]) * smask[t];
    }
    int w = t >> 5, lane = t & 31;
    for (int i = w; i < NJ; i += 8) {
        float a0=0.f,a1=0.f,a2=0.f,a3=0.f,a4=0.f,a5=0.f;
        const float* hp = g_h + (size_t)(b*NJ + i)*HS;
        for (int k = lane; k < HS; k += 32) {
            float hv = hp[k];
            const float* wr = Wo + k*7;
            a0 += hv*wr[0]; a1 += hv*wr[1]; a2 += hv*wr[2];
            a3 += hv*wr[3]; a4 += hv*wr[4]; a5 += hv*wr[5];
        }
        #pragma unroll
        for (int off = 16; off > 0; off >>= 1) {
            a0 += __shfl_down_sync(0xffffffffu, a0, off);
            a1 += __shfl_down_sync(0xffffffffu, a1, off);
            a2 += __shfl_down_sync(0xffffffffu, a2, off);
            a3 += __shfl_down_sync(0xffffffffu, a3, off);
            a4 += __shfl_down_sync(0xffffffffu, a4, off);
            a5 += __shfl_down_sync(0xffffffffu, a5, off);
        }
        if (lane == 0) {
            float m = smask[i];
            float* o = out + (b*NJ+i)*9;
            o[3] = (a0 + bo[0]) * m;
            o[4] = (a1 + bo[1]) * m;
            o[5] = (a2 + bo[2]) * m;
            o[6] = (a3 + bo[3]) * m;
            o[7] = (a4 + bo[4]) * m;
            o[8] = (a5 + bo[5]) * m;
        }
    }
}

// ---------------- launch ----------------
extern "C" void kernel_launch(void* const* d_in, const int* in_sizes, int n_in,
                              void* d_out, int out_size) {
    (void)in_sizes; (void)n_in; (void)out_size;
    const float* t       = (const float*)d_in[0];
    const float* xh      = (const float*)d_in[1];
    const float* nm      = (const float*)d_in[2];
    const float* em      = (const float*)d_in[3];
    const float* rep     = (const float*)d_in[4];
    const float* W_embed = (const float*)d_in[5];
    const float* b_embed = (const float*)d_in[6];
    const float* W_rep   = (const float*)d_in[7];
    const float* b_rep   = (const float*)d_in[8];
    const float* We1     = (const float*)d_in[9];
    const float* be1     = (const float*)d_in[10];
    const float* We2     = (const float*)d_in[11];
    const float* be2     = (const float*)d_in[12];
    const float* Wn1     = (const float*)d_in[13];
    const float* bn1     = (const float*)d_in[14];
    const float* Wn2     = (const float*)d_in[15];
    const float* bn2     = (const float*)d_in[16];
    const float* Wc1     = (const float*)d_in[17];
    const float* bc1     = (const float*)d_in[18];
    const float* Wc2     = (const float*)d_in[19];
    const float* bc2     = (const float*)d_in[20];
    const float* Wc3     = (const float*)d_in[21];
    const float* W_out   = (const float*)d_in[22];
    const float* b_out   = (const float*)d_in[23];
    float* out = (float*)d_out;

    static bool attr_done = false;
    if (!attr_done) {
        cudaFuncSetAttribute(k_fused, cudaFuncAttributeMaxDynamicSharedMemorySize, FUSED_BYTES);
        cudaFuncSetAttribute(k_pqm,   cudaFuncAttributeMaxDynamicSharedMemorySize, PQM_BYTES);
        cudaFuncSetAttribute(k_nodem, cudaFuncAttributeMaxDynamicSharedMemorySize, NODEM_BYTES);
        attr_done = true;
    }

    k_prepall<<<dim3(8, 8, 61), dim3(32, 8)>>>(We2, Wc2, We1, Wc1, Wn1, Wn2,
                                               xh, nm, t, W_embed, b_embed,
                                               rep, W_rep, b_rep);
    k_pqm<<<dim3(GBLK, 2, 1), 256, PQM_BYTES>>>(0, be1, -1, nullptr);

    int k = 0;
    for (int l = 0; l < NLAY; l++) {
        k_fused<<<BSZ*22, 256, FUSED_BYTES>>>(We1 + (size_t)k*514*HS, k,
                                              be2 + k*HS, em, nullptr, nullptr, 0,
                                              (l > 0) ? 1 : 0);
        k_nodem<<<GBLK, 256, NODEM_BYTES>>>(k, bn1 + k*HS, bn2 + k*HS, nm);
        k_pqm<<<dim3(GBLK, 2, 1), 256, PQM_BYTES>>>(k + 1, be1 + (size_t)(k+1)*HS,
                                                    -1, nullptr);
        k++;
        k_fused<<<BSZ*22, 256, FUSED_BYTES>>>(We1 + (size_t)k*514*HS, k,
                                              be2 + k*HS, em, nullptr, nullptr, 0, 0);
        k_nodem<<<GBLK, 256, NODEM_BYTES>>>(k, bn1 + k*HS, bn2 + k*HS, nm);
        if (l < NLAY - 1) {
            k_pqm<<<dim3(GBLK, 2, 2), 256, PQM_BYTES>>>(8 + l, bc1 + (size_t)l*HS,
                                                        k + 1, be1 + (size_t)(k+1)*HS);
        } else {
            k_pqm<<<dim3(GBLK, 2, 1), 256, PQM_BYTES>>>(8 + l, bc1 + (size_t)l*HS,
                                                        -1, nullptr);
        }
        k++;
        k_fused<<<BSZ*22, 256, FUSED_BYTES>>>(Wc1 + (size_t)l*514*HS, 8 + l,
                                              bc2 + l*HS, em, Wc3 + (size_t)l*HS, nm, 1, 0);
    }
    k_out<<<BSZ, 256>>>(nm, W_out, b_out, out);
}

// round 17
// speedup vs baseline: 1.3583x; 1.1545x over previous
#include <cuda_runtime.h>
#include <cuda_bf16.h>
#include <cstdint>

#define BSZ 64
#define NJ  44
#define HS  256
#define REPF 512
#define NLAY 4
#define NROWS (BSZ*NJ)
#define RPB 32
#define GBLK 88

// ---------------- persistent device state ----------------
__device__ float g_h[NROWS*HS];
__device__ float g_agg[NROWS*HS];
__device__ float g_P[NROWS*HS];
__device__ float g_Q[NROWS*HS];
__device__ float g_P2[NROWS*HS];
__device__ float g_Q2[NROWS*HS];
__device__ float g_x[NROWS*3];
__device__ float g_x0[NROWS*3];
__device__ float g_d0[BSZ*NJ*NJ];
__device__ unsigned int g_W2T [12*256*128];     // bf16x2 [m][n][kpair] (edge layer2)
__device__ unsigned int g_WpqT[12*2*256*128];   // bf16 pair(k,k+4) [m][half][n][ku]
__device__ unsigned int g_Wn1T[8*256*256];      // bf16 pair(k,k+4) [m][n][ku] K=512
__device__ unsigned int g_Wn2T[8*256*128];      // bf16 pair(k,k+4) [m][n][ku] K=256

__device__ __forceinline__ float silu_f(float x) {
    return x / (1.0f + __expf(-x));
}
__device__ __forceinline__ float silu_t(float x) {
    float t;
    asm("tanh.approx.f32 %0, %1;" : "=f"(t) : "f"(0.5f*x));
    return 0.5f*x*(1.0f + t);
}
__device__ __forceinline__ unsigned int packbf(float lo, float hi) {
    __nv_bfloat162 h2 = __floats2bfloat162_rn(lo, hi);
    return *(unsigned int*)&h2;
}
__device__ __forceinline__ unsigned int f2tf32(float v) {
    unsigned int u;
    asm("cvt.rna.tf32.f32 %0, %1;" : "=r"(u) : "f"(v));
    return u;
}
__device__ __forceinline__ uint32_t sptr(const void* p) {
    uint32_t a;
    asm("{ .reg .u64 t; cvta.to.shared.u64 t, %1; cvt.u32.u64 %0, t; }" : "=r"(a) : "l"(p));
    return a;
}
__device__ __forceinline__ void mma16(float c[4], unsigned a0, unsigned a1,
                                      unsigned a2, unsigned a3,
                                      unsigned b0, unsigned b1) {
    asm volatile("mma.sync.aligned.m16n8k16.row.col.f32.bf16.bf16.f32 "
        "{%0,%1,%2,%3}, {%4,%5,%6,%7}, {%8,%9}, {%0,%1,%2,%3};"
        : "+f"(c[0]), "+f"(c[1]), "+f"(c[2]), "+f"(c[3])
        : "r"(a0), "r"(a1), "r"(a2), "r"(a3), "r"(b0), "r"(b1));
}
__device__ __forceinline__ void mma8(float c[4], unsigned a0, unsigned a1,
                                     unsigned a2, unsigned a3,
                                     unsigned b0, unsigned b1) {
    asm volatile("mma.sync.aligned.m16n8k8.row.col.f32.tf32.tf32.f32 "
        "{%0,%1,%2,%3}, {%4,%5,%6,%7}, {%8,%9}, {%0,%1,%2,%3};"
        : "+f"(c[0]), "+f"(c[1]), "+f"(c[2]), "+f"(c[3])
        : "r"(a0), "r"(a1), "r"(a2), "r"(a3), "r"(b0), "r"(b1));
}
#define LDSM4(r0, r1, r2, r3, addr) \
    asm volatile("ldmatrix.sync.aligned.m8n8.x4.shared.b16 {%0,%1,%2,%3}, [%4];" \
        : "=r"(r0), "=r"(r1), "=r"(r2), "=r"(r3) : "r"(addr))
#define CPA16(dst, src) asm volatile("cp.async.cg.shared.global [%0], [%1], 16;" :: "r"(dst), "l"(src) : "memory")
#define CPA_COMMIT()    asm volatile("cp.async.commit_group;" ::: "memory")
#define CPA_WAIT0()     asm volatile("cp.async.wait_group 0;" ::: "memory")

// ---------------- weight prep + init (merged, z-dispatch) ----------------
__global__ void k_prepall(const float* __restrict__ We2, const float* __restrict__ Wc2,
                          const float* __restrict__ We1, const float* __restrict__ Wc1,
                          const float* __restrict__ Wn1, const float* __restrict__ Wn2,
                          const float* __restrict__ xh, const float* __restrict__ nm,
                          const float* __restrict__ tt,
                          const float* __restrict__ We, const float* __restrict__ be,
                          const float* __restrict__ rep, const float* __restrict__ Wr,
                          const float* __restrict__ br) {
    __shared__ float tile[32][33];
    __shared__ float sr[REPF];
    __shared__ float srp[HS];
    __shared__ float sf[NJ*8];
    __shared__ float sx[NJ*3];
    int z = blockIdx.z;
    int tx = threadIdx.x, ty = threadIdx.y;
    int tid = ty*32 + tx;
    if (z == 60) {
        int b = blockIdx.y*8 + blockIdx.x;
        int c = tid;
        sr[c]       = rep[b*REPF + c];
        sr[c + 256] = rep[b*REPF + 256 + c];
        __syncthreads();
        {
            float a0=0.f,a1=0.f,a2=0.f,a3=0.f;
            const float* w = Wr + c;
            #pragma unroll 4
            for (int k = 0; k < REPF; k += 4) {
                a0 += sr[k+0]*w[(k+0)*HS];
                a1 += sr[k+1]*w[(k+1)*HS];
                a2 += sr[k+2]*w[(k+2)*HS];
                a3 += sr[k+3]*w[(k+3)*HS];
            }
            srp[c] = br[c] + be[c] + ((a0+a1)+(a2+a3));
        }
        if (c < NJ) {
            float m = nm[b*NJ + c];
            const float* row = xh + (b*NJ + c)*9;
            #pragma unroll
            for (int d = 0; d < 3; d++) {
                float xv = row[d] * m;
                g_x0[(b*NJ+c)*3 + d] = xv;
                g_x [(b*NJ+c)*3 + d] = xv;
                sx[c*3 + d] = xv;
            }
            #pragma unroll
            for (int k = 0; k < 6; k++) sf[c*8 + k] = row[3+k] * m;
            sf[c*8 + 6] = tt[b];
        }
        __syncthreads();
        {
            float w[7];
            #pragma unroll
            for (int k = 0; k < 7; k++) w[k] = We[k*HS + c];
            for (int i = 0; i < NJ; i++) {
                float a = srp[c];
                #pragma unroll
                for (int k = 0; k < 7; k++) a += sf[i*8 + k] * w[k];
                g_h[(size_t)(b*NJ + i)*HS + c] = a;
            }
        }
        for (int idx = c; idx < NJ*NJ; idx += 256) {
            int i = idx / NJ, j = idx % NJ;
            float dx = sx[i*3+0]-sx[j*3+0];
            float dy = sx[i*3+1]-sx[j*3+1];
            float dz = sx[i*3+2]-sx[j*3+2];
            g_d0[b*NJ*NJ + idx] = dx*dx + dy*dy + dz*dz;
        }
        return;
    }
    int k0 = blockIdx.x*32, n0 = blockIdx.y*32;
    if (z < 12) {
        int m = z;
        const float* src = (m < 8) ? We2 + (size_t)m*HS*HS : Wc2 + (size_t)(m-8)*HS*HS;
        unsigned int* dst = g_W2T + (size_t)m*256*128;
        #pragma unroll
        for (int q = 0; q < 4; q++)
            tile[ty + 8*q][tx] = src[(size_t)(k0 + ty + 8*q)*HS + n0 + tx];
        __syncthreads();
        for (int o = tid; o < 512; o += 256) {
            int nl = o >> 4, p = o & 15;
            dst[(size_t)(n0 + nl)*128 + (k0 >> 1) + p] = packbf(tile[2*p][nl], tile[2*p+1][nl]);
        }
        return;
    }
    int v = z - 12;
    const float* src; unsigned int* dst; int stride, koff;
    if (v < 24) {
        int m = v >> 1, half = v & 1;
        src = ((m < 8) ? We1 + (size_t)m*514*HS : Wc1 + (size_t)(m-8)*514*HS)
              + (size_t)half*HS*HS;
        dst = g_WpqT + ((size_t)m*2 + half)*32768; stride = 128; koff = 0;
    } else if (v < 40) {
        int u = v - 24, m = u >> 1, kh = u & 1;
        src = Wn1 + (size_t)m*512*HS + (size_t)kh*HS*HS;
        dst = g_Wn1T + (size_t)m*65536; stride = 256; koff = kh*128;
    } else {
        int m = v - 40;
        src = Wn2 + (size_t)m*HS*HS;
        dst = g_Wn2T + (size_t)m*32768; stride = 128; koff = 0;
    }
    #pragma unroll
    for (int q = 0; q < 4; q++)
        tile[ty + 8*q][tx] = src[(size_t)(k0 + ty + 8*q)*HS + n0 + tx];
    __syncthreads();
    // pack pairs (k, k+4) within each ks-group of 8 -> [n][ks*4 + m]
    for (int o = tid; o < 512; o += 256) {
        int nl = o >> 4, p = o & 15;
        int ks = p >> 2, m2 = p & 3;
        dst[(size_t)(n0 + nl)*stride + koff + (k0 >> 1) + p] =
            packbf(tile[ks*8 + m2][nl], tile[ks*8 + m2 + 4][nl]);
    }
}

// ---------------- k_fused smem layout (M=96: 2 edges/block) ----------------
#define F_OD   22912
#define F_OD0  23008
#define F_OMK  23104
#define F_OPS  23200
#define F_OPHI 23968
#define F_SX   24064
#define FUSED_FLOATS 24200
#define FUSED_BYTES (FUSED_FLOATS*4)
#define PQM_BYTES   ((RPB*260 + 2*256*20)*4)
#define NODEM_BYTES ((RPB*516 + 2*256*20 + RPB*260)*4)

// =====================================================================
// Fused edge/coord MLP; block = (b, i-pair): M=96 rows, N=256.
// =====================================================================
__global__ __launch_bounds__(256, 2) void k_fused(
    const float* __restrict__ W1,
    int mW2,
    const float* __restrict__ b2,
    const float* __restrict__ em,
    const float* __restrict__ W3,
    const float* __restrict__ nm,
    int mode, int pqbuf)
{
    extern __shared__ float S[];
    unsigned int* As = (unsigned int*)S;           // [96][132]
    unsigned int* Bs = As + 96*132;                // 2 x [256][20]
    const unsigned int* W2T = g_W2T + (size_t)mW2*256*128;
    const float* Pp = pqbuf ? g_P2 : g_P;
    const float* Qp = pqbuf ? g_Q2 : g_Q;

    int tid = threadIdx.x, warp = tid >> 5, lane = tid & 31;
    int lane4 = lane >> 2, lanem = lane & 3;
    int b = blockIdx.x / 22, pr = blockIdx.x % 22;
    int i0 = 2*pr;
    uint32_t bsm = sptr(Bs);
    uint32_t asmb = sptr(As);
    int cn = tid >> 2, cq = (tid & 3)*4;

    #pragma unroll
    for (int r = 0; r < 4; r++) {
        int nr = cn + r*64;
        CPA16(bsm + (nr*20 + cq)*4, &W2T[(size_t)nr*128 + cq]);
    }
    CPA_COMMIT();

    if (tid < 132) S[F_SX + tid] = g_x[b*NJ*3 + tid];
    if (tid < 96) {
        int g = tid / 48, j = tid % 48;
        float d0v = 0.f, mv = 0.f;
        if (j < NJ) {
            int e = (b*NJ + i0 + g)*NJ + j;
            d0v = g_d0[e]; mv = em[e];
        }
        S[F_OD0 + tid] = d0v; S[F_OMK + tid] = mv;
    }
    __syncthreads();
    if (tid < 96) {
        int g = tid / 48, j = tid % 48;
        float r = 0.f;
        if (j < NJ) {
            int i = i0 + g;
            float dx = S[F_SX + i*3+0] - S[F_SX + j*3+0];
            float dy = S[F_SX + i*3+1] - S[F_SX + j*3+1];
            float dz = S[F_SX + i*3+2] - S[F_SX + j*3+2];
            r = dx*dx + dy*dy + dz*dz;
        }
        S[F_OD + tid] = r;
    }
    __syncthreads();

    // ---- phase 1 ----
    {
        int cp = tid & 127, jh = tid >> 7;
        float2 Pv0 = *(const float2*)&Pp[(size_t)(b*NJ + i0    )*HS + 2*cp];
        float2 Pv1 = *(const float2*)&Pp[(size_t)(b*NJ + i0 + 1)*HS + 2*cp];
        float2 wdv = *(const float2*)&W1[512*HS + 2*cp];
        float2 wd0v= *(const float2*)&W1[513*HS + 2*cp];
        const float* qbase = Qp + (size_t)b*NJ*HS + 2*cp;
        int j0 = jh * 22;
        #pragma unroll
        for (int batch = 0; batch < 2; batch++) {
            float2 qv[11];
            #pragma unroll
            for (int u = 0; u < 11; u++)
                qv[u] = *(const float2*)&qbase[(size_t)(j0 + batch*11 + u)*HS];
            #pragma unroll
            for (int u = 0; u < 11; u++) {
                int j = j0 + batch*11 + u;
                float dj0 = S[F_OD + j],      d0j0 = S[F_OD0 + j];
                float dj1 = S[F_OD + 48 + j], d0j1 = S[F_OD0 + 48 + j];
                float base0 = qv[u].x, base1 = qv[u].y;
                float v00 = Pv0.x + base0 + wdv.x*dj0 + wd0v.x*d0j0;
                float v01 = Pv0.y + base1 + wdv.y*dj0 + wd0v.y*d0j0;
                float v10 = Pv1.x + base0 + wdv.x*dj1 + wd0v.x*d0j1;
                float v11 = Pv1.y + base1 + wdv.y*dj1 + wd0v.y*d0j1;
                As[j*132 + cp]        = packbf(silu_t(v00), silu_t(v01));
                As[(48 + j)*132 + cp] = packbf(silu_t(v10), silu_t(v11));
            }
        }
        for (int p = tid; p < 4*132; p += 256) {
            As[44*132 + p] = 0u;
            As[92*132 + p] = 0u;
        }
    }
    CPA_WAIT0();
    __syncthreads();

    // ---- phase 2 ----
    float acc[6][4][4];
    #pragma unroll
    for (int mt = 0; mt < 6; mt++)
        #pragma unroll
        for (int nt = 0; nt < 4; nt++)
            #pragma unroll
            for (int q = 0; q < 4; q++) acc[mt][nt][q] = 0.f;

    int l7 = lane & 7, sel = lane >> 3;
    uint32_t abase = asmb + ((((sel & 1)*8 + l7)*132) + (sel >> 1)*4)*4;
    uint32_t baddr[2];
    #pragma unroll
    for (int t = 0; t < 2; t++)
        baddr[t] = bsm + (((warp*32 + t*16 + (sel >> 1)*8 + l7)*20) + (sel & 1)*4)*4;

    for (int kc = 0; kc < 8; kc++) {
        if (kc < 7) {
            uint32_t dsm = bsm + (((kc+1) & 1) ? 256*20*4 : 0);
            #pragma unroll
            for (int r = 0; r < 4; r++) {
                int nr = cn + r*64;
                CPA16(dsm + (nr*20 + cq)*4, &W2T[(size_t)nr*128 + (kc+1)*16 + cq]);
            }
            CPA_COMMIT();
        }
        uint32_t boff = (kc & 1) ? 256*20*4 : 0;
        #pragma unroll
        for (int s = 0; s < 2; s++) {
            uint32_t koff = (uint32_t)(kc*16 + s*8)*4;
            unsigned int bb[8];
            LDSM4(bb[0], bb[1], bb[2], bb[3], baddr[0] + boff + s*8*4);
            LDSM4(bb[4], bb[5], bb[6], bb[7], baddr[1] + boff + s*8*4);
            #pragma unroll
            for (int mt = 0; mt < 6; mt++) {
                unsigned int a0, a1, a2, a3;
                LDSM4(a0, a1, a2, a3, abase + (uint32_t)mt*16*132*4 + koff);
                mma16(acc[mt][0], a0, a1, a2, a3, bb[0], bb[1]);
                mma16(acc[mt][1], a0, a1, a2, a3, bb[2], bb[3]);
                mma16(acc[mt][2], a0, a1, a2, a3, bb[4], bb[5]);
                mma16(acc[mt][3], a0, a1, a2, a3, bb[6], bb[7]);
            }
        }
        if (kc < 7) CPA_WAIT0();
        __syncthreads();
    }

    // ---- epilogue ----
    float msk[12];
    #pragma unroll
    for (int mt = 0; mt < 6; mt++) {
        msk[2*mt]   = S[F_OMK + mt*16 + lane4];
        msk[2*mt+1] = S[F_OMK + mt*16 + lane4 + 8];
    }
    if (mode == 0) {
        #pragma unroll
        for (int g = 0; g < 2; g++) {
            size_t rowbase = (size_t)(b*NJ + i0 + g)*HS;
            #pragma unroll
            for (int nt = 0; nt < 4; nt++) {
                int n = warp*32 + nt*8 + lanem*2;
                float2 bb = *(const float2*)&b2[n];
                float s0 = 0.f, s1 = 0.f;
                #pragma unroll
                for (int mm = 0; mm < 3; mm++) {
                    int mt = g*3 + mm;
                    s0 += silu_t(acc[mt][nt][0] + bb.x)*msk[2*mt]
                        + silu_t(acc[mt][nt][2] + bb.x)*msk[2*mt+1];
                    s1 += silu_t(acc[mt][nt][1] + bb.y)*msk[2*mt]
                        + silu_t(acc[mt][nt][3] + bb.y)*msk[2*mt+1];
                }
                #pragma unroll
                for (int off = 4; off <= 16; off <<= 1) {
                    s0 += __shfl_xor_sync(0xffffffffu, s0, off);
                    s1 += __shfl_xor_sync(0xffffffffu, s1, off);
                }
                if (lane4 == 0)
                    *(float2*)&g_agg[rowbase + n] = make_float2(s0*0.01f, s1*0.01f);
            }
        }
    } else {
        float ph[12];
        #pragma unroll
        for (int q = 0; q < 12; q++) ph[q] = 0.f;
        #pragma unroll
        for (int nt = 0; nt < 4; nt++) {
            int n = warp*32 + nt*8 + lanem*2;
            float2 bb = *(const float2*)&b2[n];
            float2 w3 = *(const float2*)&W3[n];
            #pragma unroll
            for (int mt = 0; mt < 6; mt++) {
                ph[2*mt]   += silu_t(acc[mt][nt][0] + bb.x)*w3.x
                            + silu_t(acc[mt][nt][1] + bb.y)*w3.y;
                ph[2*mt+1] += silu_t(acc[mt][nt][2] + bb.x)*w3.x
                            + silu_t(acc[mt][nt][3] + bb.y)*w3.y;
            }
        }
        #pragma unroll
        for (int q = 0; q < 12; q++) {
            ph[q] += __shfl_xor_sync(0xffffffffu, ph[q], 1);
            ph[q] += __shfl_xor_sync(0xffffffffu, ph[q], 2);
        }
        if (lanem == 0) {
            #pragma unroll
            for (int mt = 0; mt < 6; mt++) {
                S[F_OPS + warp*96 + mt*16 + lane4]     = ph[2*mt];
                S[F_OPS + warp*96 + mt*16 + lane4 + 8] = ph[2*mt+1];
            }
        }
        __syncthreads();
        if (tid < 96) {
            float p = 0.f;
            #pragma unroll
            for (int w = 0; w < 8; w++) p += S[F_OPS + w*96 + tid];
            S[F_OPHI + tid] = p * S[F_OMK + tid];
        }
        __syncthreads();
        if (tid < 64) {
            int pair = tid >> 3, t8 = tid & 7;
            int pc = (pair < 6) ? pair : 0;
            int g = pc / 3, d = pc % 3;
            int i = i0 + g;
            float s = 0.f;
            for (int j = t8; j < NJ; j += 8) {
                float r = S[F_OD + g*48 + j];
                float inv = rsqrtf(r + 1e-8f);
                s += (S[F_SX + i*3 + d] - S[F_SX + j*3 + d]) * inv
                     * S[F_OPHI + g*48 + j];
            }
            s += __shfl_down_sync(0xffffffffu, s, 4);
            s += __shfl_down_sync(0xffffffffu, s, 2);
            s += __shfl_down_sync(0xffffffffu, s, 1);
            if (t8 == 0 && pair < 6) {
                float m = nm[b*NJ + i];
                int xi = (b*NJ + i)*3 + d;
                g_x[xi] = (g_x[xi] + s*0.01f) * m;
            }
        }
    }
}

// =====================================================================
// P/Q projection via tf32 mma. A raw fp32 cp.async; B bf16-packed pairs
// extracted to tf32 via shift. grid (88, 2, nsets).
// =====================================================================
__global__ __launch_bounds__(256) void k_pqm(
    int mWA, const float* __restrict__ bA,
    int mWB, const float* __restrict__ bB)
{
    extern __shared__ float S[];
    unsigned int* As = (unsigned int*)S;     // [32][260]
    unsigned int* Bs = As + RPB*260;         // 2 x [256][20]
    int tid = threadIdx.x, warp = tid >> 5, lane = tid & 31;
    int lane4 = lane >> 2, lanem = lane & 3;
    int r0 = blockIdx.x * RPB, half = blockIdx.y, set = blockIdx.z;
    int mW = set ? mWB : mWA;
    const float* b1 = set ? bB : bA;
    const unsigned int* BT = g_WpqT + ((size_t)mW*2 + half)*32768;
    uint32_t bsm = sptr(Bs);
    uint32_t asmu = sptr(As);

    #pragma unroll
    for (int q = 0; q < 4; q++)
        CPA16(bsm + (tid*20 + q*4)*4, &BT[(size_t)tid*128 + q*4]);
    {
        int row = tid >> 3, t8 = tid & 7;
        const float* srcrow = g_h + (size_t)(r0 + row)*HS + t8*32;
        uint32_t dstrow = asmu + (row*260 + t8*32)*4;
        #pragma unroll
        for (int q = 0; q < 8; q++)
            CPA16(dstrow + q*16, srcrow + q*4);
    }
    CPA_COMMIT();
    CPA_WAIT0();
    __syncthreads();

    float acc[2][4][4];
    #pragma unroll
    for (int mt = 0; mt < 2; mt++)
        #pragma unroll
        for (int nt = 0; nt < 4; nt++)
            #pragma unroll
            for (int q = 0; q < 4; q++) acc[mt][nt][q] = 0.f;

    for (int kc = 0; kc < 8; kc++) {
        if (kc < 7) {
            uint32_t dsm = bsm + (((kc+1) & 1) ? 256*20*4 : 0);
            #pragma unroll
            for (int q = 0; q < 4; q++)
                CPA16(dsm + (tid*20 + q*4)*4, &BT[(size_t)tid*128 + (kc+1)*16 + q*4]);
            CPA_COMMIT();
        }
        unsigned int* Bcur = Bs + (kc & 1)*(256*20);
        #pragma unroll
        for (int ks = 0; ks < 4; ks++) {
            int pb = ks*8;
            unsigned int bf0[4], bf1[4];
            #pragma unroll
            for (int nt = 0; nt < 4; nt++) {
                int n = warp*32 + nt*8 + lane4;
                unsigned int bp = Bcur[n*20 + ks*4 + lanem];
                bf0[nt] = bp << 16;
                bf1[nt] = bp & 0xffff0000u;
            }
            #pragma unroll
            for (int mt = 0; mt < 2; mt++) {
                int r = mt*16 + lane4;
                int kA = kc*32 + pb + lanem;
                unsigned int a0 = As[r*260 + kA];
                unsigned int a1 = As[(r+8)*260 + kA];
                unsigned int a2 = As[r*260 + kA + 4];
                unsigned int a3 = As[(r+8)*260 + kA + 4];
                #pragma unroll
                for (int nt = 0; nt < 4; nt++)
                    mma8(acc[mt][nt], a0, a1, a2, a3, bf0[nt], bf1[nt]);
            }
        }
        if (kc < 7) CPA_WAIT0();
        __syncthreads();
    }

    float* outp = half ? (set ? g_Q2 : g_Q) : (set ? g_P2 : g_P);
    #pragma unroll
    for (int mt = 0; mt < 2; mt++) {
        int r = mt*16 + lane4;
        #pragma unroll
        for (int nt = 0; nt < 4; nt++) {
            int n = warp*32 + nt*8 + lanem*2;
            float2 bb = half ? make_float2(0.f, 0.f) : *(const float2*)&b1[n];
            *(float2*)&outp[(size_t)(r0+r)*HS + n] =
                make_float2(acc[mt][nt][0] + bb.x, acc[mt][nt][1] + bb.y);
            *(float2*)&outp[(size_t)(r0+r+8)*HS + n] =
                make_float2(acc[mt][nt][2] + bb.x, acc[mt][nt][3] + bb.y);
        }
    }
}

// =====================================================================
// Node MLP via tf32 mma, 2 layers + residual. B bf16-packed pairs.
// =====================================================================
__global__ __launch_bounds__(256) void k_nodem(
    int m, const float* __restrict__ b1, const float* __restrict__ b2,
    const float* __restrict__ nm)
{
    extern __shared__ float S[];
    unsigned int* A1 = (unsigned int*)S;     // [32][516]
    unsigned int* Bs = A1 + RPB*516;         // 2 x [256][20]
    unsigned int* A2 = Bs + 2*256*20;        // [32][260]
    const unsigned int* B1T = g_Wn1T + (size_t)m*65536;
    const unsigned int* B2T = g_Wn2T + (size_t)m*32768;
    uint32_t bsm = sptr(Bs);
    uint32_t a1u = sptr(A1);

    int tid = threadIdx.x, warp = tid >> 5, lane = tid & 31;
    int lane4 = lane >> 2, lanem = lane & 3;
    int r0 = blockIdx.x * RPB;

    #pragma unroll
    for (int q = 0; q < 4; q++)
        CPA16(bsm + (tid*20 + q*4)*4, &B1T[(size_t)tid*256 + q*4]);
    {
        int row = tid >> 3, t8 = tid & 7;
        const float* hrow = g_h   + (size_t)(r0 + row)*HS;
        const float* arow = g_agg + (size_t)(r0 + row)*HS;
        uint32_t dstrow = a1u + (row*516)*4;
        #pragma unroll
        for (int q = 0; q < 8; q++) {
            int foff = q*32 + t8*4;
            CPA16(dstrow + foff*4, hrow + foff);
        }
        #pragma unroll
        for (int q = 8; q < 16; q++) {
            int foff = q*32 + t8*4;
            CPA16(dstrow + foff*4, arow + (foff - 256));
        }
    }
    CPA_COMMIT();
    CPA_WAIT0();
    __syncthreads();

    float acc[2][4][4];
    #pragma unroll
    for (int mt = 0; mt < 2; mt++)
        #pragma unroll
        for (int nt = 0; nt < 4; nt++)
            #pragma unroll
            for (int q = 0; q < 4; q++) acc[mt][nt][q] = 0.f;

    for (int kc = 0; kc < 16; kc++) {
        if (kc < 15) {
            uint32_t dsm = bsm + (((kc+1) & 1) ? 256*20*4 : 0);
            #pragma unroll
            for (int q = 0; q < 4; q++)
                CPA16(dsm + (tid*20 + q*4)*4, &B1T[(size_t)tid*256 + (kc+1)*16 + q*4]);
            CPA_COMMIT();
        }
        unsigned int* Bcur = Bs + (kc & 1)*(256*20);
        #pragma unroll
        for (int ks = 0; ks < 4; ks++) {
            int pb = ks*8;
            unsigned int bf0[4], bf1[4];
            #pragma unroll
            for (int nt = 0; nt < 4; nt++) {
                int n = warp*32 + nt*8 + lane4;
                unsigned int bp = Bcur[n*20 + ks*4 + lanem];
                bf0[nt] = bp << 16;
                bf1[nt] = bp & 0xffff0000u;
            }
            #pragma unroll
            for (int mt = 0; mt < 2; mt++) {
                int r = mt*16 + lane4;
                int kA = kc*32 + pb + lanem;
                unsigned int a0 = A1[r*516 + kA];
                unsigned int a1 = A1[(r+8)*516 + kA];
                unsigned int a2 = A1[r*516 + kA + 4];
                unsigned int a3 = A1[(r+8)*516 + kA + 4];
                #pragma unroll
                for (int nt = 0; nt < 4; nt++)
                    mma8(acc[mt][nt], a0, a1, a2, a3, bf0[nt], bf1[nt]);
            }
        }
        if (kc < 15) CPA_WAIT0();
        __syncthreads();
    }

    #pragma unroll
    for (int q = 0; q < 4; q++)
        CPA16(bsm + (tid*20 + q*4)*4, &B2T[(size_t)tid*128 + q*4]);
    CPA_COMMIT();
    #pragma unroll
    for (int mt = 0; mt < 2; mt++) {
        int r = mt*16 + lane4;
        #pragma unroll
        for (int nt = 0; nt < 4; nt++) {
            int n = warp*32 + nt*8 + lanem*2;
            float2 bb = *(const float2*)&b1[n];
            A2[r*260 + n]       = f2tf32(silu_f(acc[mt][nt][0] + bb.x));
            A2[r*260 + n + 1]   = f2tf32(silu_f(acc[mt][nt][1] + bb.y));
            A2[(r+8)*260 + n]   = f2tf32(silu_f(acc[mt][nt][2] + bb.x));
            A2[(r+8)*260 + n+1] = f2tf32(silu_f(acc[mt][nt][3] + bb.y));
        }
    }
    #pragma unroll
    for (int mt = 0; mt < 2; mt++)
        #pragma unroll
        for (int nt = 0; nt < 4; nt++)
            #pragma unroll
            for (int q = 0; q < 4; q++) acc[mt][nt][q] = 0.f;
    CPA_WAIT0();
    __syncthreads();

    for (int kc = 0; kc < 8; kc++) {
        if (kc < 7) {
            uint32_t dsm = bsm + (((kc+1) & 1) ? 256*20*4 : 0);
            #pragma unroll
            for (int q = 0; q < 4; q++)
                CPA16(dsm + (tid*20 + q*4)*4, &B2T[(size_t)tid*128 + (kc+1)*16 + q*4]);
            CPA_COMMIT();
        }
        unsigned int* Bcur = Bs + (kc & 1)*(256*20);
        #pragma unroll
        for (int ks = 0; ks < 4; ks++) {
            int pb = ks*8;
            unsigned int bf0[4], bf1[4];
            #pragma unroll
            for (int nt = 0; nt < 4; nt++) {
                int n = warp*32 + nt*8 + lane4;
                unsigned int bp = Bcur[n*20 + ks*4 + lanem];
                bf0[nt] = bp << 16;
                bf1[nt] = bp & 0xffff0000u;
            }
            #pragma unroll
            for (int mt = 0; mt < 2; mt++) {
                int r = mt*16 + lane4;
                int kA = kc*32 + pb + lanem;
                unsigned int a0 = A2[r*260 + kA];
                unsigned int a1 = A2[(r+8)*260 + kA];
                unsigned int a2 = A2[r*260 + kA + 4];
                unsigned int a3 = A2[(r+8)*260 + kA + 4];
                #pragma unroll
                for (int nt = 0; nt < 4; nt++)
                    mma8(acc[mt][nt], a0, a1, a2, a3, bf0[nt], bf1[nt]);
            }
        }
        if (kc < 7) CPA_WAIT0();
        __syncthreads();
    }

    #pragma unroll
    for (int mt = 0; mt < 2; mt++) {
        int r = mt*16 + lane4;
        #pragma unroll
        for (int nt = 0; nt < 4; nt++) {
            int n = warp*32 + nt*8 + lanem*2;
            float2 bb = *(const float2*)&b2[n];
            int gr = r0 + r;
            {
                float mk = nm[gr];
                float2 old = *(float2*)&g_h[(size_t)gr*HS + n];
                *(float2*)&g_h[(size_t)gr*HS + n] =
                    make_float2((old.x + bb.x + acc[mt][nt][0])*mk,
                                (old.y + bb.y + acc[mt][nt][1])*mk);
            }
            int gr2 = gr + 8;
            {
                float mk = nm[gr2];
                float2 old = *(float2*)&g_h[(size_t)gr2*HS + n];
                *(float2*)&g_h[(size_t)gr2*HS + n] =
                    make_float2((old.x + bb.x + acc[mt][nt][2])*mk,
                                (old.y + bb.y + acc[mt][nt][3])*mk);
            }
        }
    }
}

// ---------------- output head ----------------
__global__ __launch_bounds__(256) void k_out(const float* __restrict__ nm,
                                             const float* __restrict__ Wo,
                                             const float* __restrict__ bo,
                                             float* __restrict__ out) {
    int b = blockIdx.x, t = threadIdx.x;
    __shared__ float svel[NJ*3];
    __shared__ float smask[NJ];
    __shared__ float smean[3];
    if (t < NJ) {
        float m = nm[b*NJ + t];
        smask[t] = m;
        #pragma unroll
        for (int d = 0; d < 3; d++)
            svel[t*3+d] = (g_x[(b*NJ+t)*3+d] - g_x0[(b*NJ+t)*3+d]) * m;
    }
    __syncthreads();
    if (t == 0) {
        float s0=0.f,s1=0.f,s2=0.f,n=0.f;
        for (int j = 0; j < NJ; j++) {
            s0 += svel[j*3+0]; s1 += svel[j*3+1]; s2 += svel[j*3+2];
            n  += smask[j];
        }
        smean[0] = s0/n; smean[1] = s1/n; smean[2] = s2/n;
    }
    __syncthreads();
    if (t < NJ) {
        #pragma unroll
        for (int d = 0; d < 3; d++)
            out[(b*NJ+t)*9 + d] = (svel[t*3+d] - smean[d]) * smask[t];
    }
    int w = t >> 5, lane = t & 31;
    for (int i = w; i < NJ; i += 8) {
        float a0=0.f,a1=0.f,a2=0.f,a3=0.f,a4=0.f,a5=0.f;
        const float* hp = g_h + (size_t)(b*NJ + i)*HS;
        for (int k = lane; k < HS; k += 32) {
            float hv = hp[k];
            const float* wr = Wo + k*7;
            a0 += hv*wr[0]; a1 += hv*wr[1]; a2 += hv*wr[2];
            a3 += hv*wr[3]; a4 += hv*wr[4]; a5 += hv*wr[5];
        }
        #pragma unroll
        for (int off = 16; off > 0; off >>= 1) {
            a0 += __shfl_down_sync(0xffffffffu, a0, off);
            a1 += __shfl_down_sync(0xffffffffu, a1, off);
            a2 += __shfl_down_sync(0xffffffffu, a2, off);
            a3 += __shfl_down_sync(0xffffffffu, a3, off);
            a4 += __shfl_down_sync(0xffffffffu, a4, off);
            a5 += __shfl_down_sync(0xffffffffu, a5, off);
        }
        if (lane == 0) {
            float m = smask[i];
            float* o = out + (b*NJ+i)*9;
            o[3] = (a0 + bo[0]) * m;
            o[4] = (a1 + bo[1]) * m;
            o[5] = (a2 + bo[2]) * m;
            o[6] = (a3 + bo[3]) * m;
            o[7] = (a4 + bo[4]) * m;
            o[8] = (a5 + bo[5]) * m;
        }
    }
}

// ---------------- launch ----------------
extern "C" void kernel_launch(void* const* d_in, const int* in_sizes, int n_in,
                              void* d_out, int out_size) {
    (void)in_sizes; (void)n_in; (void)out_size;
    const float* t       = (const float*)d_in[0];
    const float* xh      = (const float*)d_in[1];
    const float* nm      = (const float*)d_in[2];
    const float* em      = (const float*)d_in[3];
    const float* rep     = (const float*)d_in[4];
    const float* W_embed = (const float*)d_in[5];
    const float* b_embed = (const float*)d_in[6];
    const float* W_rep   = (const float*)d_in[7];
    const float* b_rep   = (const float*)d_in[8];
    const float* We1     = (const float*)d_in[9];
    const float* be1     = (const float*)d_in[10];
    const float* We2     = (const float*)d_in[11];
    const float* be2     = (const float*)d_in[12];
    const float* Wn1     = (const float*)d_in[13];
    const float* bn1     = (const float*)d_in[14];
    const float* Wn2     = (const float*)d_in[15];
    const float* bn2     = (const float*)d_in[16];
    const float* Wc1     = (const float*)d_in[17];
    const float* bc1     = (const float*)d_in[18];
    const float* Wc2     = (const float*)d_in[19];
    const float* bc2     = (const float*)d_in[20];
    const float* Wc3     = (const float*)d_in[21];
    const float* W_out   = (const float*)d_in[22];
    const float* b_out   = (const float*)d_in[23];
    float* out = (float*)d_out;

    static bool attr_done = false;
    if (!attr_done) {
        cudaFuncSetAttribute(k_fused, cudaFuncAttributeMaxDynamicSharedMemorySize, FUSED_BYTES);
        cudaFuncSetAttribute(k_pqm,   cudaFuncAttributeMaxDynamicSharedMemorySize, PQM_BYTES);
        cudaFuncSetAttribute(k_nodem, cudaFuncAttributeMaxDynamicSharedMemorySize, NODEM_BYTES);
        attr_done = true;
    }

    k_prepall<<<dim3(8, 8, 61), dim3(32, 8)>>>(We2, Wc2, We1, Wc1, Wn1, Wn2,
                                               xh, nm, t, W_embed, b_embed,
                                               rep, W_rep, b_rep);
    k_pqm<<<dim3(GBLK, 2, 1), 256, PQM_BYTES>>>(0, be1, -1, nullptr);

    int k = 0;
    for (int l = 0; l < NLAY; l++) {
        k_fused<<<BSZ*22, 256, FUSED_BYTES>>>(We1 + (size_t)k*514*HS, k,
                                              be2 + k*HS, em, nullptr, nullptr, 0,
                                              (l > 0) ? 1 : 0);
        k_nodem<<<GBLK, 256, NODEM_BYTES>>>(k, bn1 + k*HS, bn2 + k*HS, nm);
        k_pqm<<<dim3(GBLK, 2, 1), 256, PQM_BYTES>>>(k + 1, be1 + (size_t)(k+1)*HS,
                                                    -1, nullptr);
        k++;
        k_fused<<<BSZ*22, 256, FUSED_BYTES>>>(We1 + (size_t)k*514*HS, k,
                                              be2 + k*HS, em, nullptr, nullptr, 0, 0);
        k_nodem<<<GBLK, 256, NODEM_BYTES>>>(k, bn1 + k*HS, bn2 + k*HS, nm);
        if (l < NLAY - 1) {
            k_pqm<<<dim3(GBLK, 2, 2), 256, PQM_BYTES>>>(8 + l, bc1 + (size_t)l*HS,
                                                        k + 1, be1 + (size_t)(k+1)*HS);
        } else {
            k_pqm<<<dim3(GBLK, 2, 1), 256, PQM_BYTES>>>(8 + l, bc1 + (size_t)l*HS,
                                                        -1, nullptr);
        }
        k++;
        k_fused<<<BSZ*22, 256, FUSED_BYTES>>>(Wc1 + (size_t)l*514*HS, 8 + l,
                                              bc2 + l*HS, em, Wc3 + (size_t)l*HS, nm, 1, 0);
    }
    k_out<<<BSZ, 256>>>(nm, W_out, b_out, out);
}